// round 1
// baseline (speedup 1.0000x reference)
#include <cuda_runtime.h>
#include <cstdint>

#define TTOK 8192
#define DMODEL 1024
#define DFF 4096
#define NEXP 8
#define CAPACITY 2560
#define NSLOT (TTOK*2)
#define CLAMPV 10000.0f
#define LDA 20

// ---------------- scratch (static device globals; allocation-free) ----------------
__device__ float g_xn[TTOK*DMODEL];                 // normalized activations
__device__ float g_h[NEXP*CAPACITY*DFF];            // silu(g)*u per buffer row
__device__ float g_y[NEXP*CAPACITY*DMODEL];         // expert outputs per buffer row
__device__ int   g_slotExpert[NSLOT];
__device__ float g_slotWeight[NSLOT];
__device__ int   g_slotDest[NSLOT];
__device__ int   g_rowToken[NEXP*CAPACITY];
__device__ int   g_blockHist[64*8];
__device__ int   g_blockBase[64*8];
__device__ int   g_mcount[8];

// ---------------- helpers ----------------
__device__ __forceinline__ uint32_t f2tf32(float x){
  uint32_t r; asm("cvt.rna.tf32.f32 %0, %1;" : "=r"(r) : "f"(x)); return r;
}

__device__ __forceinline__ void mma_tf32(float* d, const uint32_t* a, uint32_t b0, uint32_t b1){
  asm volatile("mma.sync.aligned.m16n8k8.row.col.f32.tf32.tf32.f32 "
    "{%0,%1,%2,%3}, {%4,%5,%6,%7}, {%8,%9}, {%0,%1,%2,%3};\n"
    : "+f"(d[0]),"+f"(d[1]),"+f"(d[2]),"+f"(d[3])
    : "r"(a[0]),"r"(a[1]),"r"(a[2]),"r"(a[3]),"r"(b0),"r"(b1));
}

// ---------------- kernel 1: LayerNorm + router logits + softmax + top-2 ----------------
__global__ __launch_bounds__(256) void ln_router_kernel(
    const float* __restrict__ x, const float* __restrict__ gamma,
    const float* __restrict__ beta, const float* __restrict__ Wr)
{
  __shared__ float sx[DMODEL];
  __shared__ float rs[8], rss[8];
  __shared__ float slog[8];
  __shared__ float smu, srstd;
  int t = blockIdx.x, tid = threadIdx.x;
  int w = tid >> 5, lane = tid & 31;

  float4 v = ((const float4*)x)[(size_t)t*256 + tid];
  float s  = v.x+v.y+v.z+v.w;
  float ss = v.x*v.x+v.y*v.y+v.z*v.z+v.w*v.w;
  #pragma unroll
  for (int o=16;o>0;o>>=1){
    s  += __shfl_down_sync(0xffffffffu, s, o);
    ss += __shfl_down_sync(0xffffffffu, ss, o);
  }
  if (lane==0){ rs[w]=s; rss[w]=ss; }
  __syncthreads();
  if (tid==0){
    float S=0.f, SS=0.f;
    #pragma unroll
    for (int i=0;i<8;i++){ S+=rs[i]; SS+=rss[i]; }
    float mu = S * (1.0f/DMODEL);
    float var = SS * (1.0f/DMODEL) - mu*mu;
    smu = mu; srstd = rsqrtf(var + 1e-5f);
  }
  __syncthreads();
  float mu = smu, rstd = srstd;
  float4 gm = ((const float4*)gamma)[tid];
  float4 bt = ((const float4*)beta)[tid];
  float4 xn;
  xn.x = (v.x-mu)*rstd*gm.x + bt.x;
  xn.y = (v.y-mu)*rstd*gm.y + bt.y;
  xn.z = (v.z-mu)*rstd*gm.z + bt.z;
  xn.w = (v.w-mu)*rstd*gm.w + bt.w;
  ((float4*)sx)[tid] = xn;
  ((float4*)(g_xn + (size_t)t*DMODEL))[tid] = xn;
  __syncthreads();

  // router: warp w computes logit for expert w
  const float* wr = Wr + w*DMODEL;
  float acc = 0.f;
  for (int d=lane; d<DMODEL; d+=32) acc += sx[d]*wr[d];
  #pragma unroll
  for (int o=16;o>0;o>>=1) acc += __shfl_down_sync(0xffffffffu, acc, o);
  if (lane==0) slog[w] = fminf(fmaxf(acc, -CLAMPV), CLAMPV);
  __syncthreads();

  if (tid==0){
    float p[8];
    float m = slog[0];
    #pragma unroll
    for (int e=1;e<8;e++) m = fmaxf(m, slog[e]);
    float den=0.f;
    #pragma unroll
    for (int e=0;e<8;e++){ p[e]=expf(slog[e]-m); den+=p[e]; }
    float inv = 1.f/(den + 1e-12f);
    #pragma unroll
    for (int e=0;e<8;e++) p[e]*=inv;
    int i0=0;
    #pragma unroll
    for (int e=1;e<8;e++) if (p[e]>p[i0]) i0=e;
    int i1 = (i0==0)?1:0;
    #pragma unroll
    for (int e=0;e<8;e++) if (e!=i0 && p[e]>p[i1]) i1=e;
    g_slotExpert[2*t]   = i0; g_slotWeight[2*t]   = p[i0];
    g_slotExpert[2*t+1] = i1; g_slotWeight[2*t+1] = p[i1];
  }
}

// ---------------- kernel 2: per-block expert histogram ----------------
__global__ __launch_bounds__(256) void hist_kernel(){
  __shared__ int h[8];
  if (threadIdx.x < 8) h[threadIdx.x] = 0;
  __syncthreads();
  int e = g_slotExpert[blockIdx.x*256 + threadIdx.x];
  atomicAdd(&h[e], 1);
  __syncthreads();
  if (threadIdx.x < 8) g_blockHist[blockIdx.x*8 + threadIdx.x] = h[threadIdx.x];
}

// ---------------- kernel 3: prefix scan over block histograms ----------------
__global__ void scan_kernel(){
  int e = threadIdx.x;
  if (e < 8){
    int run = 0;
    for (int b=0;b<64;b++){ g_blockBase[b*8+e] = run; run += g_blockHist[b*8+e]; }
    g_mcount[e] = (run < CAPACITY) ? run : CAPACITY;
  }
}

// ---------------- kernel 4: stable rank + scatter ----------------
__global__ __launch_bounds__(256) void rank_kernel(){
  __shared__ int se[256];
  int s = blockIdx.x*256 + threadIdx.x;
  int e = g_slotExpert[s];
  se[threadIdx.x] = e;
  __syncthreads();
  int c = 0;
  for (int j=0;j<threadIdx.x;j++) c += (se[j]==e);
  int rank = g_blockBase[blockIdx.x*8 + e] + c;
  if (rank < CAPACITY){
    int dest = e*CAPACITY + rank;
    g_slotDest[s] = dest;
    g_rowToken[dest] = s >> 1;
  } else {
    g_slotDest[s] = -1;
  }
}

// ---------------- kernel 5: GEMM1 (gathered xn @ W12^T) + fused SwiGLU ----------------
// grid: (DFF/64, 20, 8), block 256. BM=128, BN=64 per matrix (g and u), BK=16.
__global__ __launch_bounds__(256) void gemm1_kernel(const float* __restrict__ W12){
  __shared__ uint32_t sA [2][128*LDA];
  __shared__ uint32_t sBg[2][64*LDA];
  __shared__ uint32_t sBu[2][64*LDA];
  __shared__ int sTok[128];

  int e  = blockIdx.z;
  int m0 = blockIdx.y*128;
  if (m0 >= g_mcount[e]) return;
  int n0 = blockIdx.x*64;
  int tid = threadIdx.x;

  if (tid < 128) sTok[tid] = g_rowToken[e*CAPACITY + m0 + tid];
  __syncthreads();

  int lr = tid >> 2;        // 0..63
  int lc = (tid & 3) * 4;   // 0,4,8,12
  const float* Wg = W12 + (size_t)e*(2*DFF)*DMODEL + (size_t)n0*DMODEL;
  const float* Wu = Wg + (size_t)DFF*DMODEL;
  const float* A0 = g_xn + (size_t)sTok[lr]*DMODEL + lc;
  const float* A1 = g_xn + (size_t)sTok[64+lr]*DMODEL + lc;
  const float* Bg = Wg + (size_t)lr*DMODEL + lc;
  const float* Bu = Wu + (size_t)lr*DMODEL + lc;

  float accG[2][4][4], accU[2][4][4];
  #pragma unroll
  for (int a=0;a<2;a++)
    #pragma unroll
    for (int b=0;b<4;b++)
      #pragma unroll
      for (int c=0;c<4;c++){ accG[a][b][c]=0.f; accU[a][b][c]=0.f; }

  float4 ra0, ra1, rbg, rbu;
  ra0 = *(const float4*)(A0);
  ra1 = *(const float4*)(A1);
  rbg = *(const float4*)(Bg);
  rbu = *(const float4*)(Bu);
  {
    uint4 u;
    u.x=f2tf32(ra0.x); u.y=f2tf32(ra0.y); u.z=f2tf32(ra0.z); u.w=f2tf32(ra0.w);
    *(uint4*)&sA[0][lr*LDA+lc] = u;
    u.x=f2tf32(ra1.x); u.y=f2tf32(ra1.y); u.z=f2tf32(ra1.z); u.w=f2tf32(ra1.w);
    *(uint4*)&sA[0][(64+lr)*LDA+lc] = u;
    u.x=f2tf32(rbg.x); u.y=f2tf32(rbg.y); u.z=f2tf32(rbg.z); u.w=f2tf32(rbg.w);
    *(uint4*)&sBg[0][lr*LDA+lc] = u;
    u.x=f2tf32(rbu.x); u.y=f2tf32(rbu.y); u.z=f2tf32(rbu.z); u.w=f2tf32(rbu.w);
    *(uint4*)&sBu[0][lr*LDA+lc] = u;
  }
  __syncthreads();

  int w = tid >> 5, lane = tid & 31;
  int wm = (w>>1)*32, wn = (w&1)*32;
  int gg = lane >> 2, tg = lane & 3;

  const int KT = DMODEL/16;
  for (int kt=0; kt<KT; ++kt){
    int cur = kt & 1;
    if (kt+1 < KT){
      int k0 = (kt+1)*16;
      ra0 = *(const float4*)(A0 + k0);
      ra1 = *(const float4*)(A1 + k0);
      rbg = *(const float4*)(Bg + k0);
      rbu = *(const float4*)(Bu + k0);
    }
    #pragma unroll
    for (int kk=0;kk<16;kk+=8){
      uint32_t af[2][4];
      #pragma unroll
      for (int mi=0;mi<2;mi++){
        int rb = wm + mi*16;
        af[mi][0] = sA[cur][(rb+gg  )*LDA + kk+tg];
        af[mi][1] = sA[cur][(rb+8+gg)*LDA + kk+tg];
        af[mi][2] = sA[cur][(rb+gg  )*LDA + kk+tg+4];
        af[mi][3] = sA[cur][(rb+8+gg)*LDA + kk+tg+4];
      }
      #pragma unroll
      for (int ni=0;ni<4;ni++){
        int cb = wn + ni*8 + gg;
        uint32_t bg0 = sBg[cur][cb*LDA + kk+tg];
        uint32_t bg1 = sBg[cur][cb*LDA + kk+tg+4];
        uint32_t bu0 = sBu[cur][cb*LDA + kk+tg];
        uint32_t bu1 = sBu[cur][cb*LDA + kk+tg+4];
        #pragma unroll
        for (int mi=0;mi<2;mi++){
          mma_tf32(accG[mi][ni], af[mi], bg0, bg1);
          mma_tf32(accU[mi][ni], af[mi], bu0, bu1);
        }
      }
    }
    if (kt+1 < KT){
      int nxt = cur ^ 1;
      uint4 u;
      u.x=f2tf32(ra0.x); u.y=f2tf32(ra0.y); u.z=f2tf32(ra0.z); u.w=f2tf32(ra0.w);
      *(uint4*)&sA[nxt][lr*LDA+lc] = u;
      u.x=f2tf32(ra1.x); u.y=f2tf32(ra1.y); u.z=f2tf32(ra1.z); u.w=f2tf32(ra1.w);
      *(uint4*)&sA[nxt][(64+lr)*LDA+lc] = u;
      u.x=f2tf32(rbg.x); u.y=f2tf32(rbg.y); u.z=f2tf32(rbg.z); u.w=f2tf32(rbg.w);
      *(uint4*)&sBg[nxt][lr*LDA+lc] = u;
      u.x=f2tf32(rbu.x); u.y=f2tf32(rbu.y); u.z=f2tf32(rbu.z); u.w=f2tf32(rbu.w);
      *(uint4*)&sBu[nxt][lr*LDA+lc] = u;
      __syncthreads();
    }
  }

  // epilogue: h = silu(g)*u
  #pragma unroll
  for (int mi=0;mi<2;mi++){
    int r0 = m0 + wm + mi*16 + gg;
    #pragma unroll
    for (int ni=0;ni<4;ni++){
      int col = n0 + wn + ni*8 + 2*tg;
      float* hp0 = g_h + (size_t)(e*CAPACITY + r0  )*DFF + col;
      float* hp1 = g_h + (size_t)(e*CAPACITY + r0+8)*DFF + col;
      float gv, uv;
      gv = accG[mi][ni][0]; uv = accU[mi][ni][0]; hp0[0] = gv*uv/(1.f+__expf(-gv));
      gv = accG[mi][ni][1]; uv = accU[mi][ni][1]; hp0[1] = gv*uv/(1.f+__expf(-gv));
      gv = accG[mi][ni][2]; uv = accU[mi][ni][2]; hp1[0] = gv*uv/(1.f+__expf(-gv));
      gv = accG[mi][ni][3]; uv = accU[mi][ni][3]; hp1[1] = gv*uv/(1.f+__expf(-gv));
    }
  }
}

// ---------------- kernel 6: GEMM2 (h @ W3^T) ----------------
// grid: (DMODEL/128, 20, 8), block 256. BM=128, BN=128, BK=16.
__global__ __launch_bounds__(256) void gemm2_kernel(const float* __restrict__ W3){
  __shared__ uint32_t sA[2][128*LDA];
  __shared__ uint32_t sB[2][128*LDA];

  int e  = blockIdx.z;
  int m0 = blockIdx.y*128;
  if (m0 >= g_mcount[e]) return;
  int n0 = blockIdx.x*128;
  int tid = threadIdx.x;

  int lr = tid >> 2;
  int lc = (tid & 3) * 4;
  const float* A0 = g_h + (size_t)(e*CAPACITY + m0 + lr     )*DFF + lc;
  const float* A1 = g_h + (size_t)(e*CAPACITY + m0 + 64 + lr)*DFF + lc;
  const float* B0 = W3 + (size_t)e*DMODEL*DFF + (size_t)(n0+lr)*DFF + lc;
  const float* B1 = B0 + (size_t)64*DFF;

  float acc[2][8][4];
  #pragma unroll
  for (int a=0;a<2;a++)
    #pragma unroll
    for (int b=0;b<8;b++)
      #pragma unroll
      for (int c=0;c<4;c++) acc[a][b][c]=0.f;

  float4 ra0, ra1, rb0, rb1;
  ra0 = *(const float4*)(A0);
  ra1 = *(const float4*)(A1);
  rb0 = *(const float4*)(B0);
  rb1 = *(const float4*)(B1);
  {
    uint4 u;
    u.x=f2tf32(ra0.x); u.y=f2tf32(ra0.y); u.z=f2tf32(ra0.z); u.w=f2tf32(ra0.w);
    *(uint4*)&sA[0][lr*LDA+lc] = u;
    u.x=f2tf32(ra1.x); u.y=f2tf32(ra1.y); u.z=f2tf32(ra1.z); u.w=f2tf32(ra1.w);
    *(uint4*)&sA[0][(64+lr)*LDA+lc] = u;
    u.x=f2tf32(rb0.x); u.y=f2tf32(rb0.y); u.z=f2tf32(rb0.z); u.w=f2tf32(rb0.w);
    *(uint4*)&sB[0][lr*LDA+lc] = u;
    u.x=f2tf32(rb1.x); u.y=f2tf32(rb1.y); u.z=f2tf32(rb1.z); u.w=f2tf32(rb1.w);
    *(uint4*)&sB[0][(64+lr)*LDA+lc] = u;
  }
  __syncthreads();

  int w = tid >> 5, lane = tid & 31;
  int wm = (w>>1)*32, wn = (w&1)*64;
  int gg = lane >> 2, tg = lane & 3;

  const int KT = DFF/16;
  for (int kt=0; kt<KT; ++kt){
    int cur = kt & 1;
    if (kt+1 < KT){
      int k0 = (kt+1)*16;
      ra0 = *(const float4*)(A0 + k0);
      ra1 = *(const float4*)(A1 + k0);
      rb0 = *(const float4*)(B0 + k0);
      rb1 = *(const float4*)(B1 + k0);
    }
    #pragma unroll
    for (int kk=0;kk<16;kk+=8){
      uint32_t af[2][4];
      #pragma unroll
      for (int mi=0;mi<2;mi++){
        int rb = wm + mi*16;
        af[mi][0] = sA[cur][(rb+gg  )*LDA + kk+tg];
        af[mi][1] = sA[cur][(rb+8+gg)*LDA + kk+tg];
        af[mi][2] = sA[cur][(rb+gg  )*LDA + kk+tg+4];
        af[mi][3] = sA[cur][(rb+8+gg)*LDA + kk+tg+4];
      }
      #pragma unroll
      for (int ni=0;ni<8;ni++){
        int cb = wn + ni*8 + gg;
        uint32_t b0 = sB[cur][cb*LDA + kk+tg];
        uint32_t b1 = sB[cur][cb*LDA + kk+tg+4];
        #pragma unroll
        for (int mi=0;mi<2;mi++) mma_tf32(acc[mi][ni], af[mi], b0, b1);
      }
    }
    if (kt+1 < KT){
      int nxt = cur ^ 1;
      uint4 u;
      u.x=f2tf32(ra0.x); u.y=f2tf32(ra0.y); u.z=f2tf32(ra0.z); u.w=f2tf32(ra0.w);
      *(uint4*)&sA[nxt][lr*LDA+lc] = u;
      u.x=f2tf32(ra1.x); u.y=f2tf32(ra1.y); u.z=f2tf32(ra1.z); u.w=f2tf32(ra1.w);
      *(uint4*)&sA[nxt][(64+lr)*LDA+lc] = u;
      u.x=f2tf32(rb0.x); u.y=f2tf32(rb0.y); u.z=f2tf32(rb0.z); u.w=f2tf32(rb0.w);
      *(uint4*)&sB[nxt][lr*LDA+lc] = u;
      u.x=f2tf32(rb1.x); u.y=f2tf32(rb1.y); u.z=f2tf32(rb1.z); u.w=f2tf32(rb1.w);
      *(uint4*)&sB[nxt][(64+lr)*LDA+lc] = u;
      __syncthreads();
    }
  }

  #pragma unroll
  for (int mi=0;mi<2;mi++){
    int r0 = m0 + wm + mi*16 + gg;
    #pragma unroll
    for (int ni=0;ni<8;ni++){
      int col = n0 + wn + ni*8 + 2*tg;
      float* yp0 = g_y + (size_t)(e*CAPACITY + r0  )*DMODEL + col;
      float* yp1 = g_y + (size_t)(e*CAPACITY + r0+8)*DMODEL + col;
      yp0[0] = acc[mi][ni][0];
      yp0[1] = acc[mi][ni][1];
      yp1[0] = acc[mi][ni][2];
      yp1[1] = acc[mi][ni][3];
    }
  }
}

// ---------------- kernel 7: weighted combine ----------------
__global__ __launch_bounds__(256) void combine_kernel(float* __restrict__ out){
  int t = blockIdx.x, tid = threadIdx.x;
  int d0 = g_slotDest[2*t], d1 = g_slotDest[2*t+1];
  float w0 = g_slotWeight[2*t], w1 = g_slotWeight[2*t+1];
  float4 acc = make_float4(0.f,0.f,0.f,0.f);
  if (d0 >= 0){
    float4 v = *(const float4*)(g_y + (size_t)d0*DMODEL + tid*4);
    acc.x += w0*v.x; acc.y += w0*v.y; acc.z += w0*v.z; acc.w += w0*v.w;
  }
  if (d1 >= 0){
    float4 v = *(const float4*)(g_y + (size_t)d1*DMODEL + tid*4);
    acc.x += w1*v.x; acc.y += w1*v.y; acc.z += w1*v.z; acc.w += w1*v.w;
  }
  ((float4*)out)[(size_t)t*256 + tid] = acc;
}

// ---------------- launch ----------------
extern "C" void kernel_launch(void* const* d_in, const int* in_sizes, int n_in,
                              void* d_out, int out_size){
  const float* x     = (const float*)d_in[0];
  const float* gamma = (const float*)d_in[1];
  const float* beta  = (const float*)d_in[2];
  const float* Wr    = (const float*)d_in[3];
  const float* W12   = (const float*)d_in[4];
  const float* W3    = (const float*)d_in[5];
  float* out = (float*)d_out;

  ln_router_kernel<<<TTOK, 256>>>(x, gamma, beta, Wr);
  hist_kernel<<<64, 256>>>();
  scan_kernel<<<1, 32>>>();
  rank_kernel<<<64, 256>>>();
  gemm1_kernel<<<dim3(DFF/64, (CAPACITY+127)/128, NEXP), 256>>>(W12);
  gemm2_kernel<<<dim3(DMODEL/128, (CAPACITY+127)/128, NEXP), 256>>>(W3);
  combine_kernel<<<TTOK, 256>>>(out);
}

// round 3
// speedup vs baseline: 1.2842x; 1.2842x over previous
#include <cuda_runtime.h>
#include <cstdint>

#define TTOK 8192
#define DMODEL 1024
#define DFF 4096
#define NEXP 8
#define CAPACITY 2560
#define NSLOT (TTOK*2)
#define CLAMPV 10000.0f

// GEMM tiling (both GEMMs): BM=128, BN=256, BK=32, 3-stage cp.async
#define PADK 36                     // padded k-stride (floats) for conflict-free LDS
#define ASTRIDE (128*PADK)          // 4608 floats
#define BSTRIDE (256*PADK)          // 9216 floats
#define STAGEF  (ASTRIDE+BSTRIDE)   // 13824 floats = 55296 B
#define NSTAGE  3
#define SMEM_BYTES (NSTAGE*STAGEF*4)  // 165888

// ---------------- scratch (static device globals; allocation-free) ----------------
__device__ float g_xn[TTOK*DMODEL];                 // normalized activations (tf32-rounded)
__device__ float g_w12r[(size_t)NEXP*2*DFF*DMODEL]; // tf32-rounded W12
__device__ float g_w3r[(size_t)NEXP*DMODEL*DFF];    // tf32-rounded W3
__device__ float g_h[(size_t)NEXP*CAPACITY*DFF];    // silu(g)*u (tf32-rounded)
__device__ int   g_slotExpert[NSLOT];
__device__ float g_slotWeight[NSLOT];
__device__ int   g_rowToken[NEXP*CAPACITY];         // token for A-gather (0 if unfilled)
__device__ int   g_rowTok2[NEXP*CAPACITY];          // token for output combine (-1 if unfilled)
__device__ float g_rowW[NEXP*CAPACITY];             // slot weight
__device__ int   g_blockHist[64*8];
__device__ int   g_blockBase[64*8];
__device__ int   g_mcount[8];

// ---------------- helpers ----------------
__device__ __forceinline__ uint32_t f2tf32(float x){
  uint32_t r; asm("cvt.rna.tf32.f32 %0, %1;" : "=r"(r) : "f"(x)); return r;
}
__device__ __forceinline__ uint32_t smem_u32(const void* p){
  uint32_t a; asm("{ .reg .u64 t; cvta.to.shared.u64 t, %1; cvt.u32.u64 %0, t; }" : "=r"(a) : "l"(p));
  return a;
}
__device__ __forceinline__ void mma_tf32(float* d, const uint32_t* a, uint32_t b0, uint32_t b1){
  asm volatile("mma.sync.aligned.m16n8k8.row.col.f32.tf32.tf32.f32 "
    "{%0,%1,%2,%3}, {%4,%5,%6,%7}, {%8,%9}, {%0,%1,%2,%3};\n"
    : "+f"(d[0]),"+f"(d[1]),"+f"(d[2]),"+f"(d[3])
    : "r"(a[0]),"r"(a[1]),"r"(a[2]),"r"(a[3]),"r"(b0),"r"(b1));
}
#define CPA(dst, src) \
  asm volatile("cp.async.cg.shared.global [%0], [%1], 16;" :: "r"(dst), "l"(src) : "memory")
#define CPA_COMMIT() asm volatile("cp.async.commit_group;" ::: "memory")
#define CPA_WAIT1()  asm volatile("cp.async.wait_group 1;" ::: "memory")

// ---------------- kernel 0: per-launch weight rounding to TF32 ----------------
__global__ __launch_bounds__(256) void convw_kernel(const float4* __restrict__ w12,
                                                    const float4* __restrict__ w3){
  const size_t N12 = (size_t)NEXP*2*DFF*DMODEL/4;
  const size_t N3  = (size_t)NEXP*DMODEL*DFF/4;
  size_t stride = (size_t)gridDim.x*blockDim.x;
  for (size_t i = (size_t)blockIdx.x*blockDim.x + threadIdx.x; i < N12+N3; i += stride){
    float4 v; float4* dst;
    if (i < N12){ v = w12[i]; dst = ((float4*)g_w12r)+i; }
    else        { v = w3[i-N12]; dst = ((float4*)g_w3r)+(i-N12); }
    float4 o;
    o.x=__uint_as_float(f2tf32(v.x)); o.y=__uint_as_float(f2tf32(v.y));
    o.z=__uint_as_float(f2tf32(v.z)); o.w=__uint_as_float(f2tf32(v.w));
    *dst = o;
  }
}

// ---------------- kernel 1: LayerNorm + router + top-2 ----------------
__global__ __launch_bounds__(256) void ln_router_kernel(
    const float* __restrict__ x, const float* __restrict__ gamma,
    const float* __restrict__ beta, const float* __restrict__ Wr)
{
  __shared__ float sx[DMODEL];
  __shared__ float rs[8], rss[8];
  __shared__ float slog[8];
  __shared__ float smu, srstd;
  int t = blockIdx.x, tid = threadIdx.x;
  int w = tid >> 5, lane = tid & 31;

  float4 v = ((const float4*)x)[(size_t)t*256 + tid];
  float s  = v.x+v.y+v.z+v.w;
  float ss = v.x*v.x+v.y*v.y+v.z*v.z+v.w*v.w;
  #pragma unroll
  for (int o=16;o>0;o>>=1){
    s  += __shfl_down_sync(0xffffffffu, s, o);
    ss += __shfl_down_sync(0xffffffffu, ss, o);
  }
  if (lane==0){ rs[w]=s; rss[w]=ss; }
  __syncthreads();
  if (tid==0){
    float S=0.f, SS=0.f;
    #pragma unroll
    for (int i=0;i<8;i++){ S+=rs[i]; SS+=rss[i]; }
    float mu = S * (1.0f/DMODEL);
    float var = SS * (1.0f/DMODEL) - mu*mu;
    smu = mu; srstd = rsqrtf(var + 1e-5f);
  }
  __syncthreads();
  float mu = smu, rstd = srstd;
  float4 gm = ((const float4*)gamma)[tid];
  float4 bt = ((const float4*)beta)[tid];
  float4 xn;
  xn.x = (v.x-mu)*rstd*gm.x + bt.x;
  xn.y = (v.y-mu)*rstd*gm.y + bt.y;
  xn.z = (v.z-mu)*rstd*gm.z + bt.z;
  xn.w = (v.w-mu)*rstd*gm.w + bt.w;
  ((float4*)sx)[tid] = xn;
  float4 xr;
  xr.x=__uint_as_float(f2tf32(xn.x)); xr.y=__uint_as_float(f2tf32(xn.y));
  xr.z=__uint_as_float(f2tf32(xn.z)); xr.w=__uint_as_float(f2tf32(xn.w));
  ((float4*)(g_xn + (size_t)t*DMODEL))[tid] = xr;
  __syncthreads();

  const float* wr = Wr + w*DMODEL;
  float acc = 0.f;
  for (int d=lane; d<DMODEL; d+=32) acc += sx[d]*wr[d];
  #pragma unroll
  for (int o=16;o>0;o>>=1) acc += __shfl_down_sync(0xffffffffu, acc, o);
  if (lane==0) slog[w] = fminf(fmaxf(acc, -CLAMPV), CLAMPV);
  __syncthreads();

  if (tid==0){
    float p[8];
    float m = slog[0];
    #pragma unroll
    for (int e=1;e<8;e++) m = fmaxf(m, slog[e]);
    float den=0.f;
    #pragma unroll
    for (int e=0;e<8;e++){ p[e]=expf(slog[e]-m); den+=p[e]; }
    float inv = 1.f/(den + 1e-12f);
    #pragma unroll
    for (int e=0;e<8;e++) p[e]*=inv;
    int i0=0;
    #pragma unroll
    for (int e=1;e<8;e++) if (p[e]>p[i0]) i0=e;
    int i1 = (i0==0)?1:0;
    #pragma unroll
    for (int e=0;e<8;e++) if (e!=i0 && p[e]>p[i1]) i1=e;
    g_slotExpert[2*t]   = i0; g_slotWeight[2*t]   = p[i0];
    g_slotExpert[2*t+1] = i1; g_slotWeight[2*t+1] = p[i1];
  }
}

// ---------------- routing bookkeeping ----------------
__global__ __launch_bounds__(256) void hist_kernel(){
  __shared__ int h[8];
  if (threadIdx.x < 8) h[threadIdx.x] = 0;
  __syncthreads();
  int e = g_slotExpert[blockIdx.x*256 + threadIdx.x];
  atomicAdd(&h[e], 1);
  __syncthreads();
  if (threadIdx.x < 8) g_blockHist[blockIdx.x*8 + threadIdx.x] = h[threadIdx.x];
}

__global__ __launch_bounds__(256) void scan_kernel(){
  int e = threadIdx.x >> 5, lane = threadIdx.x & 31;
  int b0 = 2*lane, b1 = b0+1;
  int h0 = g_blockHist[b0*8+e], h1 = g_blockHist[b1*8+e];
  int s = h0+h1, incl = s;
  #pragma unroll
  for (int o=1;o<32;o<<=1){
    int n = __shfl_up_sync(0xffffffffu, incl, o);
    if (lane >= o) incl += n;
  }
  int excl = incl - s;
  g_blockBase[b0*8+e] = excl;
  g_blockBase[b1*8+e] = excl + h0;
  if (lane == 31) g_mcount[e] = (incl < CAPACITY) ? incl : CAPACITY;
}

// zero out + init rowTok2
__global__ __launch_bounds__(256) void init_kernel(float4* __restrict__ out){
  int i = blockIdx.x*256 + threadIdx.x;
  out[i] = make_float4(0.f,0.f,0.f,0.f);
  if (i < NEXP*CAPACITY){ g_rowTok2[i] = -1; }
}

__global__ __launch_bounds__(256) void rank_kernel(){
  __shared__ int se[256];
  int s = blockIdx.x*256 + threadIdx.x;
  int e = g_slotExpert[s];
  se[threadIdx.x] = e;
  __syncthreads();
  int c = 0;
  for (int j=0;j<threadIdx.x;j++) c += (se[j]==e);
  int rank = g_blockBase[blockIdx.x*8 + e] + c;
  if (rank < CAPACITY){
    int dest = e*CAPACITY + rank;
    g_rowToken[dest] = s >> 1;
    g_rowTok2[dest]  = s >> 1;
    g_rowW[dest]     = g_slotWeight[s];
  }
}

// ---------------- GEMM1: (gathered xn) @ W12^T, 128x(128g|128u) tiles, fused SwiGLU ----------------
// grid (20, 32, 8), block 256
__global__ __launch_bounds__(256, 1) void gemm1_kernel(){
  extern __shared__ float sdyn[];
  __shared__ int sTok[128];

  int e  = blockIdx.z;
  int m0 = blockIdx.x * 128;
  if (m0 >= g_mcount[e]) return;
  int n0 = blockIdx.y * 128;     // g col base (u cols are n0..n0+127 of u half)
  int tid = threadIdx.x, w = tid >> 5, lane = tid & 31;

  if (tid < 128) sTok[tid] = g_rowToken[e*CAPACITY + m0 + tid];
  __syncthreads();

  uint32_t sbase = smem_u32(sdyn);

  // per-thread cp.async plan
  const float* srcA[4]; uint32_t dstA[4];
  #pragma unroll
  for (int i=0;i<4;i++){
    int c = tid + i*256, row = c >> 3, seg = c & 7;
    srcA[i] = g_xn + (size_t)sTok[row]*DMODEL + seg*4;
    dstA[i] = (uint32_t)(row*PADK + seg*4)*4u;
  }
  const float* srcB[8]; uint32_t dstB[8];
  #pragma unroll
  for (int i=0;i<8;i++){
    int c = tid + i*256, row = c >> 3, seg = c & 7;
    int wrow = (row < 128) ? (n0 + row) : (DFF + n0 + row - 128);
    srcB[i] = g_w12r + ((size_t)e*(2*DFF) + wrow)*DMODEL + seg*4;
    dstB[i] = (uint32_t)(ASTRIDE + row*PADK + seg*4)*4u;
  }

  const int KT = DMODEL/32;      // 32
  // prologue: stages 0,1
  #pragma unroll
  for (int st=0; st<2; st++){
    uint32_t sb = sbase + (uint32_t)st*STAGEF*4u;
    int koff = st*32;
    #pragma unroll
    for (int i=0;i<4;i++) CPA(sb + dstA[i], srcA[i] + koff);
    #pragma unroll
    for (int i=0;i<8;i++) CPA(sb + dstB[i], srcB[i] + koff);
    CPA_COMMIT();
  }

  // warp tiling: 2(m) x 4(n-pair); warp covers rows wm..wm+63, g cols wn..wn+31 and u cols wn..wn+31
  int wm = (w>>2)*64, wn = (w&3)*32;
  int gg = lane >> 2, tg = lane & 3;

  float accG[4][4][4], accU[4][4][4];
  #pragma unroll
  for (int a=0;a<4;a++)
    #pragma unroll
    for (int b=0;b<4;b++)
      #pragma unroll
      for (int c=0;c<4;c++){ accG[a][b][c]=0.f; accU[a][b][c]=0.f; }

  int stage = 0, nstage = 2;
  for (int kt=0; kt<KT; ++kt){
    CPA_WAIT1();
    __syncthreads();
    // issue stage kt+2
    if (kt+2 < KT){
      uint32_t sb = sbase + (uint32_t)nstage*STAGEF*4u;
      int koff = (kt+2)*32;
      #pragma unroll
      for (int i=0;i<4;i++) CPA(sb + dstA[i], srcA[i] + koff);
      #pragma unroll
      for (int i=0;i<8;i++) CPA(sb + dstB[i], srcB[i] + koff);
    }
    CPA_COMMIT();

    const float* S  = sdyn + stage*STAGEF;
    const float* SB = S + ASTRIDE;
    #pragma unroll
    for (int kk=0; kk<32; kk+=8){
      uint32_t af[4][4];
      #pragma unroll
      for (int mi=0;mi<4;mi++){
        int rb = wm + mi*16;
        af[mi][0] = __float_as_uint(S[(rb+gg  )*PADK + kk+tg  ]);
        af[mi][1] = __float_as_uint(S[(rb+8+gg)*PADK + kk+tg  ]);
        af[mi][2] = __float_as_uint(S[(rb+gg  )*PADK + kk+tg+4]);
        af[mi][3] = __float_as_uint(S[(rb+8+gg)*PADK + kk+tg+4]);
      }
      #pragma unroll
      for (int ni=0;ni<4;ni++){
        int cbg = wn + ni*8 + gg;
        uint32_t bg0 = __float_as_uint(SB[cbg*PADK + kk+tg  ]);
        uint32_t bg1 = __float_as_uint(SB[cbg*PADK + kk+tg+4]);
        int cbu = 128 + cbg;
        uint32_t bu0 = __float_as_uint(SB[cbu*PADK + kk+tg  ]);
        uint32_t bu1 = __float_as_uint(SB[cbu*PADK + kk+tg+4]);
        #pragma unroll
        for (int mi=0;mi<4;mi++){
          mma_tf32(accG[mi][ni], af[mi], bg0, bg1);
          mma_tf32(accU[mi][ni], af[mi], bu0, bu1);
        }
      }
    }
    stage = (stage+1==NSTAGE)?0:stage+1;
    nstage = (nstage+1==NSTAGE)?0:nstage+1;
  }

  // epilogue: h = tf32(silu(g)*u)
  #pragma unroll
  for (int mi=0;mi<4;mi++){
    int r1 = m0 + wm + mi*16 + gg;
    int r2 = r1 + 8;
    float* hp1 = g_h + (size_t)(e*CAPACITY + r1)*DFF + n0;
    float* hp2 = g_h + (size_t)(e*CAPACITY + r2)*DFF + n0;
    #pragma unroll
    for (int ni=0;ni<4;ni++){
      int col = wn + ni*8 + 2*tg;
      float g0=accG[mi][ni][0], u0=accU[mi][ni][0];
      float g1=accG[mi][ni][1], u1=accU[mi][ni][1];
      float g2=accG[mi][ni][2], u2=accU[mi][ni][2];
      float g3=accG[mi][ni][3], u3=accU[mi][ni][3];
      float2 o1, o2;
      o1.x = __uint_as_float(f2tf32(g0*u0/(1.f+__expf(-g0))));
      o1.y = __uint_as_float(f2tf32(g1*u1/(1.f+__expf(-g1))));
      o2.x = __uint_as_float(f2tf32(g2*u2/(1.f+__expf(-g2))));
      o2.y = __uint_as_float(f2tf32(g3*u3/(1.f+__expf(-g3))));
      *(float2*)(hp1 + col) = o1;
      *(float2*)(hp2 + col) = o2;
    }
  }
}

// ---------------- GEMM2: h @ W3^T, 128x256 tiles, fused weighted atomic combine ----------------
// grid (20, 4, 8), block 256
__global__ __launch_bounds__(256, 1) void gemm2_kernel(float* __restrict__ out){
  extern __shared__ float sdyn[];

  int e  = blockIdx.z;
  int m0 = blockIdx.x * 128;
  if (m0 >= g_mcount[e]) return;
  int n0 = blockIdx.y * 256;
  int tid = threadIdx.x, w = tid >> 5, lane = tid & 31;

  uint32_t sbase = smem_u32(sdyn);

  const float* srcA[4]; uint32_t dstA[4];
  #pragma unroll
  for (int i=0;i<4;i++){
    int c = tid + i*256, row = c >> 3, seg = c & 7;
    srcA[i] = g_h + (size_t)(e*CAPACITY + m0 + row)*DFF + seg*4;
    dstA[i] = (uint32_t)(row*PADK + seg*4)*4u;
  }
  const float* srcB[8]; uint32_t dstB[8];
  #pragma unroll
  for (int i=0;i<8;i++){
    int c = tid + i*256, row = c >> 3, seg = c & 7;
    srcB[i] = g_w3r + ((size_t)e*DMODEL + n0 + row)*DFF + seg*4;
    dstB[i] = (uint32_t)(ASTRIDE + row*PADK + seg*4)*4u;
  }

  const int KT = DFF/32;      // 128
  #pragma unroll
  for (int st=0; st<2; st++){
    uint32_t sb = sbase + (uint32_t)st*STAGEF*4u;
    int koff = st*32;
    #pragma unroll
    for (int i=0;i<4;i++) CPA(sb + dstA[i], srcA[i] + koff);
    #pragma unroll
    for (int i=0;i<8;i++) CPA(sb + dstB[i], srcB[i] + koff);
    CPA_COMMIT();
  }

  // warp tiling: 2(m) x 4(n): warp = 64 rows x 64 cols
  int wm = (w>>2)*64, wn = (w&3)*64;
  int gg = lane >> 2, tg = lane & 3;

  float acc[4][8][4];
  #pragma unroll
  for (int a=0;a<4;a++)
    #pragma unroll
    for (int b=0;b<8;b++)
      #pragma unroll
      for (int c=0;c<4;c++) acc[a][b][c]=0.f;

  int stage = 0, nstage = 2;
  for (int kt=0; kt<KT; ++kt){
    CPA_WAIT1();
    __syncthreads();
    if (kt+2 < KT){
      uint32_t sb = sbase + (uint32_t)nstage*STAGEF*4u;
      int koff = (kt+2)*32;
      #pragma unroll
      for (int i=0;i<4;i++) CPA(sb + dstA[i], srcA[i] + koff);
      #pragma unroll
      for (int i=0;i<8;i++) CPA(sb + dstB[i], srcB[i] + koff);
    }
    CPA_COMMIT();

    const float* S  = sdyn + stage*STAGEF;
    const float* SB = S + ASTRIDE;
    #pragma unroll
    for (int kk=0; kk<32; kk+=8){
      uint32_t af[4][4];
      #pragma unroll
      for (int mi=0;mi<4;mi++){
        int rb = wm + mi*16;
        af[mi][0] = __float_as_uint(S[(rb+gg  )*PADK + kk+tg  ]);
        af[mi][1] = __float_as_uint(S[(rb+8+gg)*PADK + kk+tg  ]);
        af[mi][2] = __float_as_uint(S[(rb+gg  )*PADK + kk+tg+4]);
        af[mi][3] = __float_as_uint(S[(rb+8+gg)*PADK + kk+tg+4]);
      }
      #pragma unroll
      for (int ni=0;ni<8;ni++){
        int cb = wn + ni*8 + gg;
        uint32_t b0 = __float_as_uint(SB[cb*PADK + kk+tg  ]);
        uint32_t b1 = __float_as_uint(SB[cb*PADK + kk+tg+4]);
        #pragma unroll
        for (int mi=0;mi<4;mi++) mma_tf32(acc[mi][ni], af[mi], b0, b1);
      }
    }
    stage = (stage+1==NSTAGE)?0:stage+1;
    nstage = (nstage+1==NSTAGE)?0:nstage+1;
  }

  // epilogue: out[token] += acc * weight (<=2 addends per element -> deterministic)
  #pragma unroll
  for (int mi=0;mi<4;mi++){
    int r1 = m0 + wm + mi*16 + gg;
    int r2 = r1 + 8;
    int t1 = g_rowTok2[e*CAPACITY + r1];
    int t2 = g_rowTok2[e*CAPACITY + r2];
    float w1 = g_rowW[e*CAPACITY + r1];
    float w2 = g_rowW[e*CAPACITY + r2];
    float* op1 = out + (size_t)t1*DMODEL + n0;
    float* op2 = out + (size_t)t2*DMODEL + n0;
    #pragma unroll
    for (int ni=0;ni<8;ni++){
      int col = wn + ni*8 + 2*tg;
      if (t1 >= 0){
        atomicAdd(op1 + col,     acc[mi][ni][0]*w1);
        atomicAdd(op1 + col + 1, acc[mi][ni][1]*w1);
      }
      if (t2 >= 0){
        atomicAdd(op2 + col,     acc[mi][ni][2]*w2);
        atomicAdd(op2 + col + 1, acc[mi][ni][3]*w2);
      }
    }
  }
}

// ---------------- launch ----------------
extern "C" void kernel_launch(void* const* d_in, const int* in_sizes, int n_in,
                              void* d_out, int out_size){
  const float* x     = (const float*)d_in[0];
  const float* gamma = (const float*)d_in[1];
  const float* beta  = (const float*)d_in[2];
  const float* Wr    = (const float*)d_in[3];
  const float* W12   = (const float*)d_in[4];
  const float* W3    = (const float*)d_in[5];
  float* out = (float*)d_out;

  cudaFuncSetAttribute(gemm1_kernel, cudaFuncAttributeMaxDynamicSharedMemorySize, SMEM_BYTES);
  cudaFuncSetAttribute(gemm2_kernel, cudaFuncAttributeMaxDynamicSharedMemorySize, SMEM_BYTES);

  convw_kernel<<<16384, 256>>>((const float4*)W12, (const float4*)W3);
  ln_router_kernel<<<TTOK, 256>>>(x, gamma, beta, Wr);
  hist_kernel<<<64, 256>>>();
  scan_kernel<<<1, 256>>>();
  init_kernel<<<TTOK, 256>>>((float4*)out);
  rank_kernel<<<64, 256>>>();
  gemm1_kernel<<<dim3(CAPACITY/128, DFF/128, NEXP), 256, SMEM_BYTES>>>();
  gemm2_kernel<<<dim3(CAPACITY/128, DMODEL/256, NEXP), 256, SMEM_BYTES>>>(out);
}

// round 4
// speedup vs baseline: 2.0220x; 1.5745x over previous
#include <cuda_runtime.h>
#include <cuda_fp16.h>
#include <cstdint>

#define TTOK 8192
#define DMODEL 1024
#define DFF 4096
#define NEXP 8
#define CAPACITY 2560
#define NSLOT (TTOK*2)
#define CLAMPV 10000.0f

// GEMM tiling: BM=128, BN=256, BK=32 (halves), 4-stage cp.async
#define PADH 40                       // halves per smem row (80 B, conflict-free)
#define ASTRIDE_B (128*80)            // 10240 B
#define BSTRIDE_B (256*80)            // 20480 B
#define STAGE_B   (ASTRIDE_B+BSTRIDE_B) // 30720 B
#define NSTAGE 4
#define SMEM_BYTES (NSTAGE*STAGE_B)   // 122880

// ---------------- scratch (static device globals; allocation-free) ----------------
__device__ __half g_xnh[(size_t)TTOK*DMODEL];          // fp16 normalized activations
__device__ __half g_w12h[(size_t)NEXP*2*DFF*DMODEL];   // fp16 W12
__device__ __half g_w3h[(size_t)NEXP*DMODEL*DFF];      // fp16 W3
__device__ __half g_h[(size_t)NEXP*CAPACITY*DFF];      // fp16 silu(g)*u
__device__ int   g_slotExpert[NSLOT];
__device__ float g_slotWeight[NSLOT];
__device__ int   g_rowToken[NEXP*CAPACITY];            // token for A-gather
__device__ int   g_rowTok2[NEXP*CAPACITY];             // token for combine (-1 unfilled)
__device__ float g_rowW[NEXP*CAPACITY];
__device__ int   g_blockHist[64*8];
__device__ int   g_blockBase[64*8];
__device__ int   g_mcount[8];

// ---------------- helpers ----------------
__device__ __forceinline__ uint32_t smem_u32(const void* p){
  uint32_t a; asm("{ .reg .u64 t; cvta.to.shared.u64 t, %1; cvt.u32.u64 %0, t; }" : "=r"(a) : "l"(p));
  return a;
}
__device__ __forceinline__ void mma_f16(float* d, const uint32_t* a, uint32_t b0, uint32_t b1){
  asm volatile("mma.sync.aligned.m16n8k16.row.col.f32.f16.f16.f32 "
    "{%0,%1,%2,%3}, {%4,%5,%6,%7}, {%8,%9}, {%0,%1,%2,%3};\n"
    : "+f"(d[0]),"+f"(d[1]),"+f"(d[2]),"+f"(d[3])
    : "r"(a[0]),"r"(a[1]),"r"(a[2]),"r"(a[3]),"r"(b0),"r"(b1));
}
#define CPA(dst, src) \
  asm volatile("cp.async.cg.shared.global [%0], [%1], 16;" :: "r"(dst), "l"(src) : "memory")
#define CPA_COMMIT() asm volatile("cp.async.commit_group;" ::: "memory")
#define CPA_WAIT2()  asm volatile("cp.async.wait_group 2;" ::: "memory")

// ---------------- kernel 0: weight conversion fp32 -> fp16 ----------------
__global__ __launch_bounds__(256) void convw_kernel(const float4* __restrict__ w12,
                                                    const float4* __restrict__ w3){
  // process 8 floats (2 float4) -> 8 halves (16B) per iteration
  const size_t N12 = (size_t)NEXP*2*DFF*DMODEL/8;
  const size_t N3  = (size_t)NEXP*DMODEL*DFF/8;
  size_t stride = (size_t)gridDim.x*blockDim.x;
  for (size_t i = (size_t)blockIdx.x*blockDim.x + threadIdx.x; i < N12+N3; i += stride){
    const float4* s; __half2* d;
    if (i < N12){ s = w12 + i*2; d = ((__half2*)g_w12h) + i*4; }
    else { size_t j = i - N12; s = w3 + j*2; d = ((__half2*)g_w3h) + j*4; }
    float4 v0 = s[0], v1 = s[1];
    __half2 o0 = __floats2half2_rn(v0.x, v0.y);
    __half2 o1 = __floats2half2_rn(v0.z, v0.w);
    __half2 o2 = __floats2half2_rn(v1.x, v1.y);
    __half2 o3 = __floats2half2_rn(v1.z, v1.w);
    d[0]=o0; d[1]=o1; d[2]=o2; d[3]=o3;
  }
}

// ---------------- kernel 1: LayerNorm + router + top-2 ----------------
__global__ __launch_bounds__(256) void ln_router_kernel(
    const float* __restrict__ x, const float* __restrict__ gamma,
    const float* __restrict__ beta, const float* __restrict__ Wr)
{
  __shared__ float sx[DMODEL];
  __shared__ float rs[8], rss[8];
  __shared__ float slog[8];
  __shared__ float smu, srstd;
  int t = blockIdx.x, tid = threadIdx.x;
  int w = tid >> 5, lane = tid & 31;

  float4 v = ((const float4*)x)[(size_t)t*256 + tid];
  float s  = v.x+v.y+v.z+v.w;
  float ss = v.x*v.x+v.y*v.y+v.z*v.z+v.w*v.w;
  #pragma unroll
  for (int o=16;o>0;o>>=1){
    s  += __shfl_down_sync(0xffffffffu, s, o);
    ss += __shfl_down_sync(0xffffffffu, ss, o);
  }
  if (lane==0){ rs[w]=s; rss[w]=ss; }
  __syncthreads();
  if (tid==0){
    float S=0.f, SS=0.f;
    #pragma unroll
    for (int i=0;i<8;i++){ S+=rs[i]; SS+=rss[i]; }
    float mu = S * (1.0f/DMODEL);
    float var = SS * (1.0f/DMODEL) - mu*mu;
    smu = mu; srstd = rsqrtf(var + 1e-5f);
  }
  __syncthreads();
  float mu = smu, rstd = srstd;
  float4 gm = ((const float4*)gamma)[tid];
  float4 bt = ((const float4*)beta)[tid];
  float4 xn;
  xn.x = (v.x-mu)*rstd*gm.x + bt.x;
  xn.y = (v.y-mu)*rstd*gm.y + bt.y;
  xn.z = (v.z-mu)*rstd*gm.z + bt.z;
  xn.w = (v.w-mu)*rstd*gm.w + bt.w;
  ((float4*)sx)[tid] = xn;
  __half2 p0 = __floats2half2_rn(xn.x, xn.y);
  __half2 p1 = __floats2half2_rn(xn.z, xn.w);
  __half2* xp = (__half2*)(g_xnh + (size_t)t*DMODEL) + tid*2;
  xp[0]=p0; xp[1]=p1;
  __syncthreads();

  const float* wr = Wr + w*DMODEL;
  float acc = 0.f;
  for (int d=lane; d<DMODEL; d+=32) acc += sx[d]*wr[d];
  #pragma unroll
  for (int o=16;o>0;o>>=1) acc += __shfl_down_sync(0xffffffffu, acc, o);
  if (lane==0) slog[w] = fminf(fmaxf(acc, -CLAMPV), CLAMPV);
  __syncthreads();

  if (tid==0){
    float p[8];
    float m = slog[0];
    #pragma unroll
    for (int e=1;e<8;e++) m = fmaxf(m, slog[e]);
    float den=0.f;
    #pragma unroll
    for (int e=0;e<8;e++){ p[e]=expf(slog[e]-m); den+=p[e]; }
    float inv = 1.f/(den + 1e-12f);
    #pragma unroll
    for (int e=0;e<8;e++) p[e]*=inv;
    int i0=0;
    #pragma unroll
    for (int e=1;e<8;e++) if (p[e]>p[i0]) i0=e;
    int i1 = (i0==0)?1:0;
    #pragma unroll
    for (int e=0;e<8;e++) if (e!=i0 && p[e]>p[i1]) i1=e;
    g_slotExpert[2*t]   = i0; g_slotWeight[2*t]   = p[i0];
    g_slotExpert[2*t+1] = i1; g_slotWeight[2*t+1] = p[i1];
  }
}

// ---------------- routing bookkeeping ----------------
__global__ __launch_bounds__(256) void hist_kernel(){
  __shared__ int h[8];
  if (threadIdx.x < 8) h[threadIdx.x] = 0;
  __syncthreads();
  int e = g_slotExpert[blockIdx.x*256 + threadIdx.x];
  atomicAdd(&h[e], 1);
  __syncthreads();
  if (threadIdx.x < 8) g_blockHist[blockIdx.x*8 + threadIdx.x] = h[threadIdx.x];
}

__global__ __launch_bounds__(256) void scan_kernel(){
  int e = threadIdx.x >> 5, lane = threadIdx.x & 31;
  int b0 = 2*lane, b1 = b0+1;
  int h0 = g_blockHist[b0*8+e], h1 = g_blockHist[b1*8+e];
  int s = h0+h1, incl = s;
  #pragma unroll
  for (int o=1;o<32;o<<=1){
    int n = __shfl_up_sync(0xffffffffu, incl, o);
    if (lane >= o) incl += n;
  }
  int excl = incl - s;
  g_blockBase[b0*8+e] = excl;
  g_blockBase[b1*8+e] = excl + h0;
  if (lane == 31) g_mcount[e] = (incl < CAPACITY) ? incl : CAPACITY;
}

__global__ __launch_bounds__(256) void init_kernel(float4* __restrict__ out){
  int i = blockIdx.x*256 + threadIdx.x;
  out[i] = make_float4(0.f,0.f,0.f,0.f);
  if (i < NEXP*CAPACITY){ g_rowTok2[i] = -1; }
}

__global__ __launch_bounds__(256) void rank_kernel(){
  __shared__ int se[256];
  int s = blockIdx.x*256 + threadIdx.x;
  int e = g_slotExpert[s];
  se[threadIdx.x] = e;
  __syncthreads();
  int c = 0;
  for (int j=0;j<threadIdx.x;j++) c += (se[j]==e);
  int rank = g_blockBase[blockIdx.x*8 + e] + c;
  if (rank < CAPACITY){
    int dest = e*CAPACITY + rank;
    g_rowToken[dest] = s >> 1;
    g_rowTok2[dest]  = s >> 1;
    g_rowW[dest]     = g_slotWeight[s];
  }
}

// ---------------- GEMM1: (gathered xn) @ W12^T fp16, fused SwiGLU ----------------
// grid (20, 32, 8), block 256. tile 128 x (128 g | 128 u), BK=32
__global__ __launch_bounds__(256, 1) void gemm1_kernel(){
  extern __shared__ __align__(16) char sdyn[];
  __shared__ int sTok[128];

  int e  = blockIdx.z;
  int m0 = blockIdx.x * 128;
  if (m0 >= g_mcount[e]) return;
  int n0 = blockIdx.y * 128;
  int tid = threadIdx.x, w = tid >> 5, lane = tid & 31;

  if (tid < 128) sTok[tid] = g_rowToken[e*CAPACITY + m0 + tid];
  __syncthreads();

  uint32_t sbase = smem_u32(sdyn);

  // cp.async plan: 16B chunks = 8 halves; rows of 32 halves = 4 segs
  const __half* srcA[2]; uint32_t dstA[2];
  #pragma unroll
  for (int i=0;i<2;i++){
    int c = tid + i*256, row = c >> 2, seg = c & 3;
    srcA[i] = g_xnh + (size_t)sTok[row]*DMODEL + seg*8;
    dstA[i] = (uint32_t)(row*80 + seg*16);
  }
  const __half* srcB[4]; uint32_t dstB[4];
  #pragma unroll
  for (int i=0;i<4;i++){
    int c = tid + i*256, row = c >> 2, seg = c & 3;
    int wrow = (row < 128) ? (n0 + row) : (DFF + n0 + row - 128);
    srcB[i] = g_w12h + ((size_t)e*(2*DFF) + wrow)*DMODEL + seg*8;
    dstB[i] = (uint32_t)(ASTRIDE_B + row*80 + seg*16);
  }

  const int KT = DMODEL/32;      // 32
  #pragma unroll
  for (int st=0; st<NSTAGE-1; st++){
    uint32_t sb = sbase + (uint32_t)st*STAGE_B;
    int koff = st*32;
    #pragma unroll
    for (int i=0;i<2;i++) CPA(sb + dstA[i], srcA[i] + koff);
    #pragma unroll
    for (int i=0;i<4;i++) CPA(sb + dstB[i], srcB[i] + koff);
    CPA_COMMIT();
  }

  int wm = (w>>2)*64, wn = (w&3)*32;
  int gg = lane >> 2, tg = lane & 3;

  float accG[4][4][4], accU[4][4][4];
  #pragma unroll
  for (int a=0;a<4;a++)
    #pragma unroll
    for (int b=0;b<4;b++)
      #pragma unroll
      for (int c=0;c<4;c++){ accG[a][b][c]=0.f; accU[a][b][c]=0.f; }

  for (int kt=0; kt<KT; ++kt){
    CPA_WAIT2();
    __syncthreads();
    if (kt+NSTAGE-1 < KT){
      uint32_t sb = sbase + (uint32_t)((kt+NSTAGE-1)&(NSTAGE-1))*STAGE_B;
      int koff = (kt+NSTAGE-1)*32;
      #pragma unroll
      for (int i=0;i<2;i++) CPA(sb + dstA[i], srcA[i] + koff);
      #pragma unroll
      for (int i=0;i<4;i++) CPA(sb + dstB[i], srcB[i] + koff);
    }
    CPA_COMMIT();

    const __half* S  = (const __half*)(sdyn + (size_t)(kt&(NSTAGE-1))*STAGE_B);
    const __half* SB = (const __half*)(sdyn + (size_t)(kt&(NSTAGE-1))*STAGE_B + ASTRIDE_B);
    #pragma unroll
    for (int kk=0; kk<32; kk+=16){
      uint32_t af[4][4];
      #pragma unroll
      for (int mi=0;mi<4;mi++){
        int rb = wm + mi*16;
        af[mi][0] = *(const uint32_t*)&S[(rb+gg  )*PADH + kk + 2*tg];
        af[mi][1] = *(const uint32_t*)&S[(rb+8+gg)*PADH + kk + 2*tg];
        af[mi][2] = *(const uint32_t*)&S[(rb+gg  )*PADH + kk + 2*tg + 8];
        af[mi][3] = *(const uint32_t*)&S[(rb+8+gg)*PADH + kk + 2*tg + 8];
      }
      #pragma unroll
      for (int ni=0;ni<4;ni++){
        int cbg = wn + ni*8 + gg;
        uint32_t bg0 = *(const uint32_t*)&SB[cbg*PADH + kk + 2*tg];
        uint32_t bg1 = *(const uint32_t*)&SB[cbg*PADH + kk + 2*tg + 8];
        int cbu = 128 + cbg;
        uint32_t bu0 = *(const uint32_t*)&SB[cbu*PADH + kk + 2*tg];
        uint32_t bu1 = *(const uint32_t*)&SB[cbu*PADH + kk + 2*tg + 8];
        #pragma unroll
        for (int mi=0;mi<4;mi++){
          mma_f16(accG[mi][ni], af[mi], bg0, bg1);
          mma_f16(accU[mi][ni], af[mi], bu0, bu1);
        }
      }
    }
  }

  // epilogue: h = fp16(silu(g)*u)
  #pragma unroll
  for (int mi=0;mi<4;mi++){
    int r1 = m0 + wm + mi*16 + gg;
    int r2 = r1 + 8;
    __half* hp1 = g_h + (size_t)(e*CAPACITY + r1)*DFF + n0;
    __half* hp2 = g_h + (size_t)(e*CAPACITY + r2)*DFF + n0;
    #pragma unroll
    for (int ni=0;ni<4;ni++){
      int col = wn + ni*8 + 2*tg;
      float g0=accG[mi][ni][0], u0=accU[mi][ni][0];
      float g1=accG[mi][ni][1], u1=accU[mi][ni][1];
      float g2=accG[mi][ni][2], u2=accU[mi][ni][2];
      float g3=accG[mi][ni][3], u3=accU[mi][ni][3];
      float h0 = g0*u0/(1.f+__expf(-g0));
      float h1 = g1*u1/(1.f+__expf(-g1));
      float h2 = g2*u2/(1.f+__expf(-g2));
      float h3 = g3*u3/(1.f+__expf(-g3));
      *(__half2*)(hp1 + col) = __floats2half2_rn(h0, h1);
      *(__half2*)(hp2 + col) = __floats2half2_rn(h2, h3);
    }
  }
}

// ---------------- GEMM2: h @ W3^T fp16, fused weighted atomic combine ----------------
// grid (20, 4, 8), block 256. tile 128 x 256, BK=32
__global__ __launch_bounds__(256, 1) void gemm2_kernel(float* __restrict__ out){
  extern __shared__ __align__(16) char sdyn[];

  int e  = blockIdx.z;
  int m0 = blockIdx.x * 128;
  if (m0 >= g_mcount[e]) return;
  int n0 = blockIdx.y * 256;
  int tid = threadIdx.x, w = tid >> 5, lane = tid & 31;

  uint32_t sbase = smem_u32(sdyn);

  const __half* srcA[2]; uint32_t dstA[2];
  #pragma unroll
  for (int i=0;i<2;i++){
    int c = tid + i*256, row = c >> 2, seg = c & 3;
    srcA[i] = g_h + (size_t)(e*CAPACITY + m0 + row)*DFF + seg*8;
    dstA[i] = (uint32_t)(row*80 + seg*16);
  }
  const __half* srcB[4]; uint32_t dstB[4];
  #pragma unroll
  for (int i=0;i<4;i++){
    int c = tid + i*256, row = c >> 2, seg = c & 3;
    srcB[i] = g_w3h + ((size_t)e*DMODEL + n0 + row)*DFF + seg*8;
    dstB[i] = (uint32_t)(ASTRIDE_B + row*80 + seg*16);
  }

  const int KT = DFF/32;     // 128
  #pragma unroll
  for (int st=0; st<NSTAGE-1; st++){
    uint32_t sb = sbase + (uint32_t)st*STAGE_B;
    int koff = st*32;
    #pragma unroll
    for (int i=0;i<2;i++) CPA(sb + dstA[i], srcA[i] + koff);
    #pragma unroll
    for (int i=0;i<4;i++) CPA(sb + dstB[i], srcB[i] + koff);
    CPA_COMMIT();
  }

  int wm = (w>>2)*64, wn = (w&3)*64;
  int gg = lane >> 2, tg = lane & 3;

  float acc[4][8][4];
  #pragma unroll
  for (int a=0;a<4;a++)
    #pragma unroll
    for (int b=0;b<8;b++)
      #pragma unroll
      for (int c=0;c<4;c++) acc[a][b][c]=0.f;

  for (int kt=0; kt<KT; ++kt){
    CPA_WAIT2();
    __syncthreads();
    if (kt+NSTAGE-1 < KT){
      uint32_t sb = sbase + (uint32_t)((kt+NSTAGE-1)&(NSTAGE-1))*STAGE_B;
      int koff = (kt+NSTAGE-1)*32;
      #pragma unroll
      for (int i=0;i<2;i++) CPA(sb + dstA[i], srcA[i] + koff);
      #pragma unroll
      for (int i=0;i<4;i++) CPA(sb + dstB[i], srcB[i] + koff);
    }
    CPA_COMMIT();

    const __half* S  = (const __half*)(sdyn + (size_t)(kt&(NSTAGE-1))*STAGE_B);
    const __half* SB = (const __half*)(sdyn + (size_t)(kt&(NSTAGE-1))*STAGE_B + ASTRIDE_B);
    #pragma unroll
    for (int kk=0; kk<32; kk+=16){
      uint32_t af[4][4];
      #pragma unroll
      for (int mi=0;mi<4;mi++){
        int rb = wm + mi*16;
        af[mi][0] = *(const uint32_t*)&S[(rb+gg  )*PADH + kk + 2*tg];
        af[mi][1] = *(const uint32_t*)&S[(rb+8+gg)*PADH + kk + 2*tg];
        af[mi][2] = *(const uint32_t*)&S[(rb+gg  )*PADH + kk + 2*tg + 8];
        af[mi][3] = *(const uint32_t*)&S[(rb+8+gg)*PADH + kk + 2*tg + 8];
      }
      #pragma unroll
      for (int ni=0;ni<8;ni++){
        int cb = wn + ni*8 + gg;
        uint32_t b0 = *(const uint32_t*)&SB[cb*PADH + kk + 2*tg];
        uint32_t b1 = *(const uint32_t*)&SB[cb*PADH + kk + 2*tg + 8];
        #pragma unroll
        for (int mi=0;mi<4;mi++) mma_f16(acc[mi][ni], af[mi], b0, b1);
      }
    }
  }

  // epilogue: out[token] += acc * weight (<=2 addends/element -> deterministic)
  #pragma unroll
  for (int mi=0;mi<4;mi++){
    int r1 = m0 + wm + mi*16 + gg;
    int r2 = r1 + 8;
    int t1 = g_rowTok2[e*CAPACITY + r1];
    int t2 = g_rowTok2[e*CAPACITY + r2];
    float w1 = g_rowW[e*CAPACITY + r1];
    float w2 = g_rowW[e*CAPACITY + r2];
    float* op1 = out + (size_t)t1*DMODEL + n0;
    float* op2 = out + (size_t)t2*DMODEL + n0;
    #pragma unroll
    for (int ni=0;ni<8;ni++){
      int col = wn + ni*8 + 2*tg;
      if (t1 >= 0){
        atomicAdd(op1 + col,     acc[mi][ni][0]*w1);
        atomicAdd(op1 + col + 1, acc[mi][ni][1]*w1);
      }
      if (t2 >= 0){
        atomicAdd(op2 + col,     acc[mi][ni][2]*w2);
        atomicAdd(op2 + col + 1, acc[mi][ni][3]*w2);
      }
    }
  }
}

// ---------------- launch ----------------
extern "C" void kernel_launch(void* const* d_in, const int* in_sizes, int n_in,
                              void* d_out, int out_size){
  const float* x     = (const float*)d_in[0];
  const float* gamma = (const float*)d_in[1];
  const float* beta  = (const float*)d_in[2];
  const float* Wr    = (const float*)d_in[3];
  const float* W12   = (const float*)d_in[4];
  const float* W3    = (const float*)d_in[5];
  float* out = (float*)d_out;

  cudaFuncSetAttribute(gemm1_kernel, cudaFuncAttributeMaxDynamicSharedMemorySize, SMEM_BYTES);
  cudaFuncSetAttribute(gemm2_kernel, cudaFuncAttributeMaxDynamicSharedMemorySize, SMEM_BYTES);

  convw_kernel<<<16384, 256>>>((const float4*)W12, (const float4*)W3);
  ln_router_kernel<<<TTOK, 256>>>(x, gamma, beta, Wr);
  hist_kernel<<<64, 256>>>();
  scan_kernel<<<1, 256>>>();
  init_kernel<<<TTOK, 256>>>((float4*)out);
  rank_kernel<<<64, 256>>>();
  gemm1_kernel<<<dim3(CAPACITY/128, DFF/128, NEXP), 256, SMEM_BYTES>>>();
  gemm2_kernel<<<dim3(CAPACITY/128, DMODEL/256, NEXP), 256, SMEM_BYTES>>>(out);
}

// round 5
// speedup vs baseline: 2.3330x; 1.1538x over previous
#include <cuda_runtime.h>
#include <cuda_fp16.h>
#include <cstdint>

#define TTOK 8192
#define DMODEL 1024
#define DFF 4096
#define NEXP 8
#define CAPACITY 2560
#define NSLOT (TTOK*2)
#define CLAMPV 10000.0f

// GEMM tiling: BM=128, BN=256, BK=32 (halves), 4-stage cp.async
#define PADH 40                       // halves per smem row (80 B, conflict-free for LDS + LDSM)
#define ASTRIDE_B (128*80)            // 10240 B
#define BSTRIDE_B (256*80)            // 20480 B
#define STAGE_B   (ASTRIDE_B+BSTRIDE_B) // 30720 B
#define NSTAGE 4
#define SMEM_BYTES (NSTAGE*STAGE_B)   // 122880

// ---------------- scratch (static device globals; allocation-free) ----------------
__device__ __half g_xnh[(size_t)TTOK*DMODEL];          // fp16 normalized activations
__device__ __half g_w12h[(size_t)NEXP*2*DFF*DMODEL];   // fp16 W12
__device__ __half g_w3h[(size_t)NEXP*DMODEL*DFF];      // fp16 W3
__device__ __half g_h[(size_t)NEXP*CAPACITY*DFF];      // fp16 silu(g)*u
__device__ int   g_slotExpert[NSLOT];
__device__ float g_slotWeight[NSLOT];
__device__ int   g_rowToken[NEXP*CAPACITY];            // token for A-gather
__device__ int   g_rowTok2[NEXP*CAPACITY];             // token for combine (-1 unfilled)
__device__ float g_rowW[NEXP*CAPACITY];
__device__ int   g_blockHist[64*8];
__device__ int   g_blockBase[64*8];
__device__ int   g_mcount[8];

// ---------------- helpers ----------------
__device__ __forceinline__ uint32_t smem_u32(const void* p){
  uint32_t a; asm("{ .reg .u64 t; cvta.to.shared.u64 t, %1; cvt.u32.u64 %0, t; }" : "=r"(a) : "l"(p));
  return a;
}
__device__ __forceinline__ void mma_f16(float* d, const uint32_t* a, uint32_t b0, uint32_t b1){
  asm volatile("mma.sync.aligned.m16n8k16.row.col.f32.f16.f16.f32 "
    "{%0,%1,%2,%3}, {%4,%5,%6,%7}, {%8,%9}, {%0,%1,%2,%3};\n"
    : "+f"(d[0]),"+f"(d[1]),"+f"(d[2]),"+f"(d[3])
    : "r"(a[0]),"r"(a[1]),"r"(a[2]),"r"(a[3]),"r"(b0),"r"(b1));
}
#define LDSM4(r0,r1,r2,r3,addr) \
  asm volatile("ldmatrix.sync.aligned.m8n8.x4.shared.b16 {%0,%1,%2,%3}, [%4];" \
    : "=r"(r0),"=r"(r1),"=r"(r2),"=r"(r3) : "r"(addr))
#define CPA(dst, src) \
  asm volatile("cp.async.cg.shared.global [%0], [%1], 16;" :: "r"(dst), "l"(src) : "memory")
#define CPA_COMMIT() asm volatile("cp.async.commit_group;" ::: "memory")
#define CPA_WAIT2()  asm volatile("cp.async.wait_group 2;" ::: "memory")

// ---------------- kernel 0: weight conversion fp32 -> fp16 ----------------
__global__ __launch_bounds__(256) void convw_kernel(const float4* __restrict__ w12,
                                                    const float4* __restrict__ w3){
  const size_t N12 = (size_t)NEXP*2*DFF*DMODEL/8;
  const size_t N3  = (size_t)NEXP*DMODEL*DFF/8;
  size_t stride = (size_t)gridDim.x*blockDim.x;
  for (size_t i = (size_t)blockIdx.x*blockDim.x + threadIdx.x; i < N12+N3; i += stride){
    const float4* s; __half2* d;
    if (i < N12){ s = w12 + i*2; d = ((__half2*)g_w12h) + i*4; }
    else { size_t j = i - N12; s = w3 + j*2; d = ((__half2*)g_w3h) + j*4; }
    float4 v0 = s[0], v1 = s[1];
    d[0] = __floats2half2_rn(v0.x, v0.y);
    d[1] = __floats2half2_rn(v0.z, v0.w);
    d[2] = __floats2half2_rn(v1.x, v1.y);
    d[3] = __floats2half2_rn(v1.z, v1.w);
  }
}

// ---------------- kernel 1: LayerNorm + router + top-2 ----------------
__global__ __launch_bounds__(256) void ln_router_kernel(
    const float* __restrict__ x, const float* __restrict__ gamma,
    const float* __restrict__ beta, const float* __restrict__ Wr)
{
  __shared__ float sx[DMODEL];
  __shared__ float rs[8], rss[8];
  __shared__ float slog[8];
  __shared__ float smu, srstd;
  int t = blockIdx.x, tid = threadIdx.x;
  int w = tid >> 5, lane = tid & 31;

  float4 v = ((const float4*)x)[(size_t)t*256 + tid];
  float s  = v.x+v.y+v.z+v.w;
  float ss = v.x*v.x+v.y*v.y+v.z*v.z+v.w*v.w;
  #pragma unroll
  for (int o=16;o>0;o>>=1){
    s  += __shfl_down_sync(0xffffffffu, s, o);
    ss += __shfl_down_sync(0xffffffffu, ss, o);
  }
  if (lane==0){ rs[w]=s; rss[w]=ss; }
  __syncthreads();
  if (tid==0){
    float S=0.f, SS=0.f;
    #pragma unroll
    for (int i=0;i<8;i++){ S+=rs[i]; SS+=rss[i]; }
    float mu = S * (1.0f/DMODEL);
    float var = SS * (1.0f/DMODEL) - mu*mu;
    smu = mu; srstd = rsqrtf(var + 1e-5f);
  }
  __syncthreads();
  float mu = smu, rstd = srstd;
  float4 gm = ((const float4*)gamma)[tid];
  float4 bt = ((const float4*)beta)[tid];
  float4 xn;
  xn.x = (v.x-mu)*rstd*gm.x + bt.x;
  xn.y = (v.y-mu)*rstd*gm.y + bt.y;
  xn.z = (v.z-mu)*rstd*gm.z + bt.z;
  xn.w = (v.w-mu)*rstd*gm.w + bt.w;
  ((float4*)sx)[tid] = xn;
  __half2 p0 = __floats2half2_rn(xn.x, xn.y);
  __half2 p1 = __floats2half2_rn(xn.z, xn.w);
  __half2* xp = (__half2*)(g_xnh + (size_t)t*DMODEL) + tid*2;
  xp[0]=p0; xp[1]=p1;
  __syncthreads();

  const float* wr = Wr + w*DMODEL;
  float acc = 0.f;
  for (int d=lane; d<DMODEL; d+=32) acc += sx[d]*wr[d];
  #pragma unroll
  for (int o=16;o>0;o>>=1) acc += __shfl_down_sync(0xffffffffu, acc, o);
  if (lane==0) slog[w] = fminf(fmaxf(acc, -CLAMPV), CLAMPV);
  __syncthreads();

  if (tid==0){
    float p[8];
    float m = slog[0];
    #pragma unroll
    for (int e=1;e<8;e++) m = fmaxf(m, slog[e]);
    float den=0.f;
    #pragma unroll
    for (int e=0;e<8;e++){ p[e]=expf(slog[e]-m); den+=p[e]; }
    float inv = 1.f/(den + 1e-12f);
    #pragma unroll
    for (int e=0;e<8;e++) p[e]*=inv;
    int i0=0;
    #pragma unroll
    for (int e=1;e<8;e++) if (p[e]>p[i0]) i0=e;
    int i1 = (i0==0)?1:0;
    #pragma unroll
    for (int e=0;e<8;e++) if (e!=i0 && p[e]>p[i1]) i1=e;
    g_slotExpert[2*t]   = i0; g_slotWeight[2*t]   = p[i0];
    g_slotExpert[2*t+1] = i1; g_slotWeight[2*t+1] = p[i1];
  }
}

// ---------------- routing bookkeeping ----------------
__global__ __launch_bounds__(256) void hist_kernel(){
  __shared__ int h[8];
  if (threadIdx.x < 8) h[threadIdx.x] = 0;
  __syncthreads();
  int e = g_slotExpert[blockIdx.x*256 + threadIdx.x];
  atomicAdd(&h[e], 1);
  __syncthreads();
  if (threadIdx.x < 8) g_blockHist[blockIdx.x*8 + threadIdx.x] = h[threadIdx.x];
}

__global__ __launch_bounds__(256) void scan_kernel(){
  int e = threadIdx.x >> 5, lane = threadIdx.x & 31;
  int b0 = 2*lane, b1 = b0+1;
  int h0 = g_blockHist[b0*8+e], h1 = g_blockHist[b1*8+e];
  int s = h0+h1, incl = s;
  #pragma unroll
  for (int o=1;o<32;o<<=1){
    int n = __shfl_up_sync(0xffffffffu, incl, o);
    if (lane >= o) incl += n;
  }
  int excl = incl - s;
  g_blockBase[b0*8+e] = excl;
  g_blockBase[b1*8+e] = excl + h0;
  if (lane == 31) g_mcount[e] = (incl < CAPACITY) ? incl : CAPACITY;
}

__global__ __launch_bounds__(256) void init_kernel(float4* __restrict__ out){
  int i = blockIdx.x*256 + threadIdx.x;
  out[i] = make_float4(0.f,0.f,0.f,0.f);
  if (i < NEXP*CAPACITY){ g_rowTok2[i] = -1; }
}

__global__ __launch_bounds__(256) void rank_kernel(){
  __shared__ int se[256];
  int s = blockIdx.x*256 + threadIdx.x;
  int e = g_slotExpert[s];
  se[threadIdx.x] = e;
  __syncthreads();
  int c = 0;
  for (int j=0;j<threadIdx.x;j++) c += (se[j]==e);
  int rank = g_blockBase[blockIdx.x*8 + e] + c;
  if (rank < CAPACITY){
    int dest = e*CAPACITY + rank;
    g_rowToken[dest] = s >> 1;
    g_rowTok2[dest]  = s >> 1;
    g_rowW[dest]     = g_slotWeight[s];
  }
}

// ---------------- GEMM1: (gathered xn) @ W12^T fp16, ldmatrix, fused SwiGLU ----------------
// grid (20, 32, 8), block 256. tile 128 x (128 g | 128 u), BK=32
__global__ __launch_bounds__(256, 1) void gemm1_kernel(){
  extern __shared__ __align__(16) char sdyn[];
  __shared__ int sTok[128];

  int e  = blockIdx.z;
  int m0 = blockIdx.x * 128;
  if (m0 >= g_mcount[e]) return;
  int n0 = blockIdx.y * 128;
  int tid = threadIdx.x, w = tid >> 5, lane = tid & 31;

  if (tid < 128) sTok[tid] = g_rowToken[e*CAPACITY + m0 + tid];
  __syncthreads();

  uint32_t sbase = smem_u32(sdyn);

  const __half* srcA[2]; uint32_t dstA[2];
  #pragma unroll
  for (int i=0;i<2;i++){
    int c = tid + i*256, row = c >> 2, seg = c & 3;
    srcA[i] = g_xnh + (size_t)sTok[row]*DMODEL + seg*8;
    dstA[i] = (uint32_t)(row*80 + seg*16);
  }
  const __half* srcB[4]; uint32_t dstB[4];
  #pragma unroll
  for (int i=0;i<4;i++){
    int c = tid + i*256, row = c >> 2, seg = c & 3;
    int wrow = (row < 128) ? (n0 + row) : (DFF + n0 + row - 128);
    srcB[i] = g_w12h + ((size_t)e*(2*DFF) + wrow)*DMODEL + seg*8;
    dstB[i] = (uint32_t)(ASTRIDE_B + row*80 + seg*16);
  }

  const int KT = DMODEL/32;      // 32
  #pragma unroll
  for (int st=0; st<NSTAGE-1; st++){
    uint32_t sb = sbase + (uint32_t)st*STAGE_B;
    int koff = st*32;
    #pragma unroll
    for (int i=0;i<2;i++) CPA(sb + dstA[i], srcA[i] + koff);
    #pragma unroll
    for (int i=0;i<4;i++) CPA(sb + dstB[i], srcB[i] + koff);
    CPA_COMMIT();
  }

  int wm = (w>>2)*64, wn = (w&3)*32;
  int gg = lane >> 2, tg = lane & 3;

  // ldmatrix per-thread address offsets (bytes, within a stage)
  uint32_t offA[4];
  #pragma unroll
  for (int mi=0;mi<4;mi++)
    offA[mi] = (uint32_t)((wm + mi*16 + (lane&15))*PADH + (lane>>4)*8)*2u;
  // B: pair p covers n-groups 2p,2p+1; lane groups: (n-lo,k-lo),(n-lo,k-hi),(n-hi,k-lo),(n-hi,k-hi)
  uint32_t offBg[2], offBu[2];
  {
    int nrow = wn + ((lane>>4)&1)*8 + (lane&7);
    int kofl = ((lane>>3)&1)*8;
    #pragma unroll
    for (int p=0;p<2;p++){
      offBg[p] = (uint32_t)(ASTRIDE_B + ((nrow + p*16)*PADH + kofl)*2);
      offBu[p] = offBg[p] + (uint32_t)(128*PADH*2);
    }
  }

  float accG[4][4][4], accU[4][4][4];
  #pragma unroll
  for (int a=0;a<4;a++)
    #pragma unroll
    for (int b=0;b<4;b++)
      #pragma unroll
      for (int c=0;c<4;c++){ accG[a][b][c]=0.f; accU[a][b][c]=0.f; }

  for (int kt=0; kt<KT; ++kt){
    CPA_WAIT2();
    __syncthreads();
    if (kt+NSTAGE-1 < KT){
      uint32_t sb = sbase + (uint32_t)((kt+NSTAGE-1)&(NSTAGE-1))*STAGE_B;
      int koff = (kt+NSTAGE-1)*32;
      #pragma unroll
      for (int i=0;i<2;i++) CPA(sb + dstA[i], srcA[i] + koff);
      #pragma unroll
      for (int i=0;i<4;i++) CPA(sb + dstB[i], srcB[i] + koff);
    }
    CPA_COMMIT();

    uint32_t sb = sbase + (uint32_t)(kt&(NSTAGE-1))*STAGE_B;
    #pragma unroll
    for (int kk=0; kk<32; kk+=16){
      uint32_t kb = sb + kk*2;
      uint32_t af[4][4];
      #pragma unroll
      for (int mi=0;mi<4;mi++)
        LDSM4(af[mi][0],af[mi][1],af[mi][2],af[mi][3], kb + offA[mi]);
      uint32_t bg[4][2], bu[4][2];
      #pragma unroll
      for (int p=0;p<2;p++){
        LDSM4(bg[2*p][0],bg[2*p][1],bg[2*p+1][0],bg[2*p+1][1], kb + offBg[p]);
        LDSM4(bu[2*p][0],bu[2*p][1],bu[2*p+1][0],bu[2*p+1][1], kb + offBu[p]);
      }
      #pragma unroll
      for (int ni=0;ni<4;ni++){
        #pragma unroll
        for (int mi=0;mi<4;mi++){
          mma_f16(accG[mi][ni], af[mi], bg[ni][0], bg[ni][1]);
          mma_f16(accU[mi][ni], af[mi], bu[ni][0], bu[ni][1]);
        }
      }
    }
  }

  // epilogue: h = fp16(silu(g)*u)
  #pragma unroll
  for (int mi=0;mi<4;mi++){
    int r1 = m0 + wm + mi*16 + gg;
    int r2 = r1 + 8;
    __half* hp1 = g_h + (size_t)(e*CAPACITY + r1)*DFF + n0;
    __half* hp2 = g_h + (size_t)(e*CAPACITY + r2)*DFF + n0;
    #pragma unroll
    for (int ni=0;ni<4;ni++){
      int col = wn + ni*8 + 2*tg;
      float g0=accG[mi][ni][0], u0=accU[mi][ni][0];
      float g1=accG[mi][ni][1], u1=accU[mi][ni][1];
      float g2=accG[mi][ni][2], u2=accU[mi][ni][2];
      float g3=accG[mi][ni][3], u3=accU[mi][ni][3];
      float h0 = g0*u0/(1.f+__expf(-g0));
      float h1 = g1*u1/(1.f+__expf(-g1));
      float h2 = g2*u2/(1.f+__expf(-g2));
      float h3 = g3*u3/(1.f+__expf(-g3));
      *(__half2*)(hp1 + col) = __floats2half2_rn(h0, h1);
      *(__half2*)(hp2 + col) = __floats2half2_rn(h2, h3);
    }
  }
}

// ---------------- GEMM2: h @ W3^T fp16, ldmatrix, fused weighted atomic combine ----------------
// grid (20, 4, 8), block 256. tile 128 x 256, BK=32
__global__ __launch_bounds__(256, 1) void gemm2_kernel(float* __restrict__ out){
  extern __shared__ __align__(16) char sdyn[];

  int e  = blockIdx.z;
  int m0 = blockIdx.x * 128;
  if (m0 >= g_mcount[e]) return;
  int n0 = blockIdx.y * 256;
  int tid = threadIdx.x, w = tid >> 5, lane = tid & 31;

  uint32_t sbase = smem_u32(sdyn);

  const __half* srcA[2]; uint32_t dstA[2];
  #pragma unroll
  for (int i=0;i<2;i++){
    int c = tid + i*256, row = c >> 2, seg = c & 3;
    srcA[i] = g_h + (size_t)(e*CAPACITY + m0 + row)*DFF + seg*8;
    dstA[i] = (uint32_t)(row*80 + seg*16);
  }
  const __half* srcB[4]; uint32_t dstB[4];
  #pragma unroll
  for (int i=0;i<4;i++){
    int c = tid + i*256, row = c >> 2, seg = c & 3;
    srcB[i] = g_w3h + ((size_t)e*DMODEL + n0 + row)*DFF + seg*8;
    dstB[i] = (uint32_t)(ASTRIDE_B + row*80 + seg*16);
  }

  const int KT = DFF/32;     // 128
  #pragma unroll
  for (int st=0; st<NSTAGE-1; st++){
    uint32_t sb = sbase + (uint32_t)st*STAGE_B;
    int koff = st*32;
    #pragma unroll
    for (int i=0;i<2;i++) CPA(sb + dstA[i], srcA[i] + koff);
    #pragma unroll
    for (int i=0;i<4;i++) CPA(sb + dstB[i], srcB[i] + koff);
    CPA_COMMIT();
  }

  int wm = (w>>2)*64, wn = (w&3)*64;
  int gg = lane >> 2, tg = lane & 3;

  uint32_t offA[4];
  #pragma unroll
  for (int mi=0;mi<4;mi++)
    offA[mi] = (uint32_t)((wm + mi*16 + (lane&15))*PADH + (lane>>4)*8)*2u;
  uint32_t offB[4];
  {
    int nrow = wn + ((lane>>4)&1)*8 + (lane&7);
    int kofl = ((lane>>3)&1)*8;
    #pragma unroll
    for (int p=0;p<4;p++)
      offB[p] = (uint32_t)(ASTRIDE_B + ((nrow + p*16)*PADH + kofl)*2);
  }

  float acc[4][8][4];
  #pragma unroll
  for (int a=0;a<4;a++)
    #pragma unroll
    for (int b=0;b<8;b++)
      #pragma unroll
      for (int c=0;c<4;c++) acc[a][b][c]=0.f;

  for (int kt=0; kt<KT; ++kt){
    CPA_WAIT2();
    __syncthreads();
    if (kt+NSTAGE-1 < KT){
      uint32_t sb = sbase + (uint32_t)((kt+NSTAGE-1)&(NSTAGE-1))*STAGE_B;
      int koff = (kt+NSTAGE-1)*32;
      #pragma unroll
      for (int i=0;i<2;i++) CPA(sb + dstA[i], srcA[i] + koff);
      #pragma unroll
      for (int i=0;i<4;i++) CPA(sb + dstB[i], srcB[i] + koff);
    }
    CPA_COMMIT();

    uint32_t sb = sbase + (uint32_t)(kt&(NSTAGE-1))*STAGE_B;
    #pragma unroll
    for (int kk=0; kk<32; kk+=16){
      uint32_t kb = sb + kk*2;
      uint32_t af[4][4];
      #pragma unroll
      for (int mi=0;mi<4;mi++)
        LDSM4(af[mi][0],af[mi][1],af[mi][2],af[mi][3], kb + offA[mi]);
      uint32_t bf[8][2];
      #pragma unroll
      for (int p=0;p<4;p++)
        LDSM4(bf[2*p][0],bf[2*p][1],bf[2*p+1][0],bf[2*p+1][1], kb + offB[p]);
      #pragma unroll
      for (int ni=0;ni<8;ni++){
        #pragma unroll
        for (int mi=0;mi<4;mi++) mma_f16(acc[mi][ni], af[mi], bf[ni][0], bf[ni][1]);
      }
    }
  }

  // epilogue: out[token] += acc * weight (<=2 addends/element -> deterministic)
  #pragma unroll
  for (int mi=0;mi<4;mi++){
    int r1 = m0 + wm + mi*16 + gg;
    int r2 = r1 + 8;
    int t1 = g_rowTok2[e*CAPACITY + r1];
    int t2 = g_rowTok2[e*CAPACITY + r2];
    float w1 = g_rowW[e*CAPACITY + r1];
    float w2 = g_rowW[e*CAPACITY + r2];
    float* op1 = out + (size_t)t1*DMODEL + n0;
    float* op2 = out + (size_t)t2*DMODEL + n0;
    #pragma unroll
    for (int ni=0;ni<8;ni++){
      int col = wn + ni*8 + 2*tg;
      if (t1 >= 0){
        atomicAdd(op1 + col,     acc[mi][ni][0]*w1);
        atomicAdd(op1 + col + 1, acc[mi][ni][1]*w1);
      }
      if (t2 >= 0){
        atomicAdd(op2 + col,     acc[mi][ni][2]*w2);
        atomicAdd(op2 + col + 1, acc[mi][ni][3]*w2);
      }
    }
  }
}

// ---------------- launch ----------------
extern "C" void kernel_launch(void* const* d_in, const int* in_sizes, int n_in,
                              void* d_out, int out_size){
  const float* x     = (const float*)d_in[0];
  const float* gamma = (const float*)d_in[1];
  const float* beta  = (const float*)d_in[2];
  const float* Wr    = (const float*)d_in[3];
  const float* W12   = (const float*)d_in[4];
  const float* W3    = (const float*)d_in[5];
  float* out = (float*)d_out;

  cudaFuncSetAttribute(gemm1_kernel, cudaFuncAttributeMaxDynamicSharedMemorySize, SMEM_BYTES);
  cudaFuncSetAttribute(gemm2_kernel, cudaFuncAttributeMaxDynamicSharedMemorySize, SMEM_BYTES);

  convw_kernel<<<16384, 256>>>((const float4*)W12, (const float4*)W3);
  ln_router_kernel<<<TTOK, 256>>>(x, gamma, beta, Wr);
  hist_kernel<<<64, 256>>>();
  scan_kernel<<<1, 256>>>();
  init_kernel<<<TTOK, 256>>>((float4*)out);
  rank_kernel<<<64, 256>>>();
  gemm1_kernel<<<dim3(CAPACITY/128, DFF/128, NEXP), 256, SMEM_BYTES>>>();
  gemm2_kernel<<<dim3(CAPACITY/128, DMODEL/256, NEXP), 256, SMEM_BYTES>>>(out);
}

// round 6
// speedup vs baseline: 2.3865x; 1.0229x over previous
#include <cuda_runtime.h>
#include <cuda_fp16.h>
#include <cstdint>

#define TTOK 8192
#define DMODEL 1024
#define DFF 4096
#define NEXP 8
#define CAPACITY 2560
#define NSLOT (TTOK*2)
#define CLAMPV 10000.0f

// GEMM tiling: BM=128, BN=256, BK=64 (halves), 3-stage cp.async
#define PADH 72                         // halves per smem row (144 B; 9 chunks -> LDSM conflict-free)
#define ROWB 144
#define ASTRIDE_B (128*ROWB)            // 18432 B
#define BSTRIDE_B (256*ROWB)            // 36864 B
#define STAGE_B   (ASTRIDE_B+BSTRIDE_B) // 55296 B
#define NSTAGE 3
#define SMEM_BYTES (NSTAGE*STAGE_B)     // 165888

// ---------------- scratch (static device globals; allocation-free) ----------------
__device__ __half g_xnh[(size_t)TTOK*DMODEL];          // fp16 normalized activations
__device__ __half g_w12h[(size_t)NEXP*2*DFF*DMODEL];   // fp16 W12
__device__ __half g_w3h[(size_t)NEXP*DMODEL*DFF];      // fp16 W3
__device__ __half g_h[(size_t)NEXP*CAPACITY*DFF];      // fp16 silu(g)*u
__device__ int   g_slotExpert[NSLOT];
__device__ float g_slotWeight[NSLOT];
__device__ int   g_rowToken[NEXP*CAPACITY];            // token for A-gather
__device__ int   g_rowTok2[NEXP*CAPACITY];             // token for combine (-1 unfilled)
__device__ float g_rowW[NEXP*CAPACITY];
__device__ int   g_blockHist[64*8];
__device__ int   g_blockBase[64*8];
__device__ int   g_mcount[8];

// ---------------- helpers ----------------
__device__ __forceinline__ uint32_t smem_u32(const void* p){
  uint32_t a; asm("{ .reg .u64 t; cvta.to.shared.u64 t, %1; cvt.u32.u64 %0, t; }" : "=r"(a) : "l"(p));
  return a;
}
__device__ __forceinline__ void mma_f16(float* d, const uint32_t* a, uint32_t b0, uint32_t b1){
  asm volatile("mma.sync.aligned.m16n8k16.row.col.f32.f16.f16.f32 "
    "{%0,%1,%2,%3}, {%4,%5,%6,%7}, {%8,%9}, {%0,%1,%2,%3};\n"
    : "+f"(d[0]),"+f"(d[1]),"+f"(d[2]),"+f"(d[3])
    : "r"(a[0]),"r"(a[1]),"r"(a[2]),"r"(a[3]),"r"(b0),"r"(b1));
}
#define LDSM4(r0,r1,r2,r3,addr) \
  asm volatile("ldmatrix.sync.aligned.m8n8.x4.shared.b16 {%0,%1,%2,%3}, [%4];" \
    : "=r"(r0),"=r"(r1),"=r"(r2),"=r"(r3) : "r"(addr))
#define CPA(dst, src) \
  asm volatile("cp.async.cg.shared.global [%0], [%1], 16;" :: "r"(dst), "l"(src) : "memory")
#define CPA_COMMIT() asm volatile("cp.async.commit_group;" ::: "memory")
#define CPA_WAIT1()  asm volatile("cp.async.wait_group 1;" ::: "memory")

// ---------------- kernel 0: weight conversion fp32 -> fp16 ----------------
__global__ __launch_bounds__(256) void convw_kernel(const float4* __restrict__ w12,
                                                    const float4* __restrict__ w3){
  const size_t N12 = (size_t)NEXP*2*DFF*DMODEL/8;
  const size_t N3  = (size_t)NEXP*DMODEL*DFF/8;
  size_t stride = (size_t)gridDim.x*blockDim.x;
  for (size_t i = (size_t)blockIdx.x*blockDim.x + threadIdx.x; i < N12+N3; i += stride){
    const float4* s; __half2* d;
    if (i < N12){ s = w12 + i*2; d = ((__half2*)g_w12h) + i*4; }
    else { size_t j = i - N12; s = w3 + j*2; d = ((__half2*)g_w3h) + j*4; }
    float4 v0 = s[0], v1 = s[1];
    d[0] = __floats2half2_rn(v0.x, v0.y);
    d[1] = __floats2half2_rn(v0.z, v0.w);
    d[2] = __floats2half2_rn(v1.x, v1.y);
    d[3] = __floats2half2_rn(v1.z, v1.w);
  }
}

// ---------------- kernel 1: LayerNorm + router + top-2 ----------------
__global__ __launch_bounds__(256) void ln_router_kernel(
    const float* __restrict__ x, const float* __restrict__ gamma,
    const float* __restrict__ beta, const float* __restrict__ Wr)
{
  __shared__ float sx[DMODEL];
  __shared__ float rs[8], rss[8];
  __shared__ float slog[8];
  __shared__ float smu, srstd;
  int t = blockIdx.x, tid = threadIdx.x;
  int w = tid >> 5, lane = tid & 31;

  float4 v = ((const float4*)x)[(size_t)t*256 + tid];
  float s  = v.x+v.y+v.z+v.w;
  float ss = v.x*v.x+v.y*v.y+v.z*v.z+v.w*v.w;
  #pragma unroll
  for (int o=16;o>0;o>>=1){
    s  += __shfl_down_sync(0xffffffffu, s, o);
    ss += __shfl_down_sync(0xffffffffu, ss, o);
  }
  if (lane==0){ rs[w]=s; rss[w]=ss; }
  __syncthreads();
  if (tid==0){
    float S=0.f, SS=0.f;
    #pragma unroll
    for (int i=0;i<8;i++){ S+=rs[i]; SS+=rss[i]; }
    float mu = S * (1.0f/DMODEL);
    float var = SS * (1.0f/DMODEL) - mu*mu;
    smu = mu; srstd = rsqrtf(var + 1e-5f);
  }
  __syncthreads();
  float mu = smu, rstd = srstd;
  float4 gm = ((const float4*)gamma)[tid];
  float4 bt = ((const float4*)beta)[tid];
  float4 xn;
  xn.x = (v.x-mu)*rstd*gm.x + bt.x;
  xn.y = (v.y-mu)*rstd*gm.y + bt.y;
  xn.z = (v.z-mu)*rstd*gm.z + bt.z;
  xn.w = (v.w-mu)*rstd*gm.w + bt.w;
  ((float4*)sx)[tid] = xn;
  __half2 p0 = __floats2half2_rn(xn.x, xn.y);
  __half2 p1 = __floats2half2_rn(xn.z, xn.w);
  __half2* xp = (__half2*)(g_xnh + (size_t)t*DMODEL) + tid*2;
  xp[0]=p0; xp[1]=p1;
  __syncthreads();

  const float* wr = Wr + w*DMODEL;
  float acc = 0.f;
  for (int d=lane; d<DMODEL; d+=32) acc += sx[d]*wr[d];
  #pragma unroll
  for (int o=16;o>0;o>>=1) acc += __shfl_down_sync(0xffffffffu, acc, o);
  if (lane==0) slog[w] = fminf(fmaxf(acc, -CLAMPV), CLAMPV);
  __syncthreads();

  if (tid==0){
    float p[8];
    float m = slog[0];
    #pragma unroll
    for (int e=1;e<8;e++) m = fmaxf(m, slog[e]);
    float den=0.f;
    #pragma unroll
    for (int e=0;e<8;e++){ p[e]=expf(slog[e]-m); den+=p[e]; }
    float inv = 1.f/(den + 1e-12f);
    #pragma unroll
    for (int e=0;e<8;e++) p[e]*=inv;
    int i0=0;
    #pragma unroll
    for (int e=1;e<8;e++) if (p[e]>p[i0]) i0=e;
    int i1 = (i0==0)?1:0;
    #pragma unroll
    for (int e=0;e<8;e++) if (e!=i0 && p[e]>p[i1]) i1=e;
    g_slotExpert[2*t]   = i0; g_slotWeight[2*t]   = p[i0];
    g_slotExpert[2*t+1] = i1; g_slotWeight[2*t+1] = p[i1];
  }
}

// ---------------- routing bookkeeping ----------------
__global__ __launch_bounds__(256) void hist_kernel(){
  __shared__ int h[8];
  if (threadIdx.x < 8) h[threadIdx.x] = 0;
  __syncthreads();
  int e = g_slotExpert[blockIdx.x*256 + threadIdx.x];
  atomicAdd(&h[e], 1);
  __syncthreads();
  if (threadIdx.x < 8) g_blockHist[blockIdx.x*8 + threadIdx.x] = h[threadIdx.x];
}

__global__ __launch_bounds__(256) void scan_kernel(){
  int e = threadIdx.x >> 5, lane = threadIdx.x & 31;
  int b0 = 2*lane, b1 = b0+1;
  int h0 = g_blockHist[b0*8+e], h1 = g_blockHist[b1*8+e];
  int s = h0+h1, incl = s;
  #pragma unroll
  for (int o=1;o<32;o<<=1){
    int n = __shfl_up_sync(0xffffffffu, incl, o);
    if (lane >= o) incl += n;
  }
  int excl = incl - s;
  g_blockBase[b0*8+e] = excl;
  g_blockBase[b1*8+e] = excl + h0;
  if (lane == 31) g_mcount[e] = (incl < CAPACITY) ? incl : CAPACITY;
}

__global__ __launch_bounds__(256) void init_kernel(float4* __restrict__ out){
  int i = blockIdx.x*256 + threadIdx.x;
  out[i] = make_float4(0.f,0.f,0.f,0.f);
  if (i < NEXP*CAPACITY){ g_rowTok2[i] = -1; }
}

__global__ __launch_bounds__(256) void rank_kernel(){
  __shared__ int se[256];
  int s = blockIdx.x*256 + threadIdx.x;
  int e = g_slotExpert[s];
  se[threadIdx.x] = e;
  __syncthreads();
  int c = 0;
  for (int j=0;j<threadIdx.x;j++) c += (se[j]==e);
  int rank = g_blockBase[blockIdx.x*8 + e] + c;
  if (rank < CAPACITY){
    int dest = e*CAPACITY + rank;
    g_rowToken[dest] = s >> 1;
    g_rowTok2[dest]  = s >> 1;
    g_rowW[dest]     = g_slotWeight[s];
  }
}

// ---------------- GEMM1: (gathered xn) @ W12^T fp16, ldmatrix, BK=64, fused SwiGLU ----------------
// grid (20, 32, 8), block 256. tile 128 x (128 g | 128 u)
__global__ __launch_bounds__(256, 1) void gemm1_kernel(){
  extern __shared__ __align__(16) char sdyn[];
  __shared__ int sTok[128];

  int e  = blockIdx.z;
  int m0 = blockIdx.x * 128;
  if (m0 >= g_mcount[e]) return;
  int n0 = blockIdx.y * 128;
  int tid = threadIdx.x, w = tid >> 5, lane = tid & 31;

  if (tid < 128) sTok[tid] = g_rowToken[e*CAPACITY + m0 + tid];
  __syncthreads();

  uint32_t sbase = smem_u32(sdyn);

  // cp.async plan: 16B chunks = 8 halves; rows of 64 halves = 8 segs
  const __half* srcA[4]; uint32_t dstA[4];
  #pragma unroll
  for (int i=0;i<4;i++){
    int c = tid + i*256, row = c >> 3, seg = c & 7;
    srcA[i] = g_xnh + (size_t)sTok[row]*DMODEL + seg*8;
    dstA[i] = (uint32_t)(row*ROWB + seg*16);
  }
  const __half* srcB[8]; uint32_t dstB[8];
  #pragma unroll
  for (int i=0;i<8;i++){
    int c = tid + i*256, row = c >> 3, seg = c & 7;
    int wrow = (row < 128) ? (n0 + row) : (DFF + n0 + row - 128);
    srcB[i] = g_w12h + ((size_t)e*(2*DFF) + wrow)*DMODEL + seg*8;
    dstB[i] = (uint32_t)(ASTRIDE_B + row*ROWB + seg*16);
  }

  const int KT = DMODEL/64;      // 16
  #pragma unroll
  for (int st=0; st<NSTAGE-1; st++){
    uint32_t sb = sbase + (uint32_t)st*STAGE_B;
    int koff = st*64;
    #pragma unroll
    for (int i=0;i<4;i++) CPA(sb + dstA[i], srcA[i] + koff);
    #pragma unroll
    for (int i=0;i<8;i++) CPA(sb + dstB[i], srcB[i] + koff);
    CPA_COMMIT();
  }

  int wm = (w>>2)*64, wn = (w&3)*32;
  int gg = lane >> 2, tg = lane & 3;

  // ldmatrix per-thread offsets (bytes within a stage)
  uint32_t offA[4];
  #pragma unroll
  for (int mi=0;mi<4;mi++)
    offA[mi] = (uint32_t)((wm + mi*16 + (lane&15))*PADH + (lane>>4)*8)*2u;
  uint32_t offBg[2], offBu[2];
  {
    int nrow = wn + ((lane>>4)&1)*8 + (lane&7);
    int kofl = ((lane>>3)&1)*8;
    #pragma unroll
    for (int p=0;p<2;p++){
      offBg[p] = (uint32_t)(ASTRIDE_B + ((nrow + p*16)*PADH + kofl)*2);
      offBu[p] = offBg[p] + (uint32_t)(128*PADH*2);
    }
  }

  float accG[4][4][4], accU[4][4][4];
  #pragma unroll
  for (int a=0;a<4;a++)
    #pragma unroll
    for (int b=0;b<4;b++)
      #pragma unroll
      for (int c=0;c<4;c++){ accG[a][b][c]=0.f; accU[a][b][c]=0.f; }

  int stage = 0, pstage = NSTAGE-1;
  for (int kt=0; kt<KT; ++kt){
    CPA_WAIT1();
    __syncthreads();
    if (kt+NSTAGE-1 < KT){
      uint32_t sb = sbase + (uint32_t)pstage*STAGE_B;
      int koff = (kt+NSTAGE-1)*64;
      #pragma unroll
      for (int i=0;i<4;i++) CPA(sb + dstA[i], srcA[i] + koff);
      #pragma unroll
      for (int i=0;i<8;i++) CPA(sb + dstB[i], srcB[i] + koff);
    }
    CPA_COMMIT();

    uint32_t sb = sbase + (uint32_t)stage*STAGE_B;
    #pragma unroll
    for (int kk=0; kk<64; kk+=16){
      uint32_t kb = sb + kk*2;
      uint32_t af[4][4];
      #pragma unroll
      for (int mi=0;mi<4;mi++)
        LDSM4(af[mi][0],af[mi][1],af[mi][2],af[mi][3], kb + offA[mi]);
      uint32_t bg[4][2], bu[4][2];
      #pragma unroll
      for (int p=0;p<2;p++){
        LDSM4(bg[2*p][0],bg[2*p][1],bg[2*p+1][0],bg[2*p+1][1], kb + offBg[p]);
        LDSM4(bu[2*p][0],bu[2*p][1],bu[2*p+1][0],bu[2*p+1][1], kb + offBu[p]);
      }
      #pragma unroll
      for (int ni=0;ni<4;ni++){
        #pragma unroll
        for (int mi=0;mi<4;mi++){
          mma_f16(accG[mi][ni], af[mi], bg[ni][0], bg[ni][1]);
          mma_f16(accU[mi][ni], af[mi], bu[ni][0], bu[ni][1]);
        }
      }
    }
    stage  = (stage+1 == NSTAGE) ? 0 : stage+1;
    pstage = (pstage+1 == NSTAGE) ? 0 : pstage+1;
  }

  // epilogue: h = fp16(silu(g)*u)
  #pragma unroll
  for (int mi=0;mi<4;mi++){
    int r1 = m0 + wm + mi*16 + gg;
    int r2 = r1 + 8;
    __half* hp1 = g_h + (size_t)(e*CAPACITY + r1)*DFF + n0;
    __half* hp2 = g_h + (size_t)(e*CAPACITY + r2)*DFF + n0;
    #pragma unroll
    for (int ni=0;ni<4;ni++){
      int col = wn + ni*8 + 2*tg;
      float g0=accG[mi][ni][0], u0=accU[mi][ni][0];
      float g1=accG[mi][ni][1], u1=accU[mi][ni][1];
      float g2=accG[mi][ni][2], u2=accU[mi][ni][2];
      float g3=accG[mi][ni][3], u3=accU[mi][ni][3];
      float h0 = g0*u0/(1.f+__expf(-g0));
      float h1 = g1*u1/(1.f+__expf(-g1));
      float h2 = g2*u2/(1.f+__expf(-g2));
      float h3 = g3*u3/(1.f+__expf(-g3));
      *(__half2*)(hp1 + col) = __floats2half2_rn(h0, h1);
      *(__half2*)(hp2 + col) = __floats2half2_rn(h2, h3);
    }
  }
}

// ---------------- GEMM2: h @ W3^T fp16, ldmatrix, BK=64, fused weighted atomic combine ----------------
// grid (20, 4, 8), block 256. tile 128 x 256
__global__ __launch_bounds__(256, 1) void gemm2_kernel(float* __restrict__ out){
  extern __shared__ __align__(16) char sdyn[];

  int e  = blockIdx.z;
  int m0 = blockIdx.x * 128;
  if (m0 >= g_mcount[e]) return;
  int n0 = blockIdx.y * 256;
  int tid = threadIdx.x, w = tid >> 5, lane = tid & 31;

  uint32_t sbase = smem_u32(sdyn);

  const __half* srcA[4]; uint32_t dstA[4];
  #pragma unroll
  for (int i=0;i<4;i++){
    int c = tid + i*256, row = c >> 3, seg = c & 7;
    srcA[i] = g_h + (size_t)(e*CAPACITY + m0 + row)*DFF + seg*8;
    dstA[i] = (uint32_t)(row*ROWB + seg*16);
  }
  const __half* srcB[8]; uint32_t dstB[8];
  #pragma unroll
  for (int i=0;i<8;i++){
    int c = tid + i*256, row = c >> 3, seg = c & 7;
    srcB[i] = g_w3h + ((size_t)e*DMODEL + n0 + row)*DFF + seg*8;
    dstB[i] = (uint32_t)(ASTRIDE_B + row*ROWB + seg*16);
  }

  const int KT = DFF/64;     // 64
  #pragma unroll
  for (int st=0; st<NSTAGE-1; st++){
    uint32_t sb = sbase + (uint32_t)st*STAGE_B;
    int koff = st*64;
    #pragma unroll
    for (int i=0;i<4;i++) CPA(sb + dstA[i], srcA[i] + koff);
    #pragma unroll
    for (int i=0;i<8;i++) CPA(sb + dstB[i], srcB[i] + koff);
    CPA_COMMIT();
  }

  int wm = (w>>2)*64, wn = (w&3)*64;
  int gg = lane >> 2, tg = lane & 3;

  uint32_t offA[4];
  #pragma unroll
  for (int mi=0;mi<4;mi++)
    offA[mi] = (uint32_t)((wm + mi*16 + (lane&15))*PADH + (lane>>4)*8)*2u;
  uint32_t offB[4];
  {
    int nrow = wn + ((lane>>4)&1)*8 + (lane&7);
    int kofl = ((lane>>3)&1)*8;
    #pragma unroll
    for (int p=0;p<4;p++)
      offB[p] = (uint32_t)(ASTRIDE_B + ((nrow + p*16)*PADH + kofl)*2);
  }

  float acc[4][8][4];
  #pragma unroll
  for (int a=0;a<4;a++)
    #pragma unroll
    for (int b=0;b<8;b++)
      #pragma unroll
      for (int c=0;c<4;c++) acc[a][b][c]=0.f;

  int stage = 0, pstage = NSTAGE-1;
  for (int kt=0; kt<KT; ++kt){
    CPA_WAIT1();
    __syncthreads();
    if (kt+NSTAGE-1 < KT){
      uint32_t sb = sbase + (uint32_t)pstage*STAGE_B;
      int koff = (kt+NSTAGE-1)*64;
      #pragma unroll
      for (int i=0;i<4;i++) CPA(sb + dstA[i], srcA[i] + koff);
      #pragma unroll
      for (int i=0;i<8;i++) CPA(sb + dstB[i], srcB[i] + koff);
    }
    CPA_COMMIT();

    uint32_t sb = sbase + (uint32_t)stage*STAGE_B;
    #pragma unroll
    for (int kk=0; kk<64; kk+=16){
      uint32_t kb = sb + kk*2;
      uint32_t af[4][4];
      #pragma unroll
      for (int mi=0;mi<4;mi++)
        LDSM4(af[mi][0],af[mi][1],af[mi][2],af[mi][3], kb + offA[mi]);
      uint32_t bf[8][2];
      #pragma unroll
      for (int p=0;p<4;p++)
        LDSM4(bf[2*p][0],bf[2*p][1],bf[2*p+1][0],bf[2*p+1][1], kb + offB[p]);
      #pragma unroll
      for (int ni=0;ni<8;ni++){
        #pragma unroll
        for (int mi=0;mi<4;mi++) mma_f16(acc[mi][ni], af[mi], bf[ni][0], bf[ni][1]);
      }
    }
    stage  = (stage+1 == NSTAGE) ? 0 : stage+1;
    pstage = (pstage+1 == NSTAGE) ? 0 : pstage+1;
  }

  // epilogue: out[token] += acc * weight (<=2 addends/element -> deterministic)
  #pragma unroll
  for (int mi=0;mi<4;mi++){
    int r1 = m0 + wm + mi*16 + gg;
    int r2 = r1 + 8;
    int t1 = g_rowTok2[e*CAPACITY + r1];
    int t2 = g_rowTok2[e*CAPACITY + r2];
    float w1 = g_rowW[e*CAPACITY + r1];
    float w2 = g_rowW[e*CAPACITY + r2];
    float* op1 = out + (size_t)t1*DMODEL + n0;
    float* op2 = out + (size_t)t2*DMODEL + n0;
    #pragma unroll
    for (int ni=0;ni<8;ni++){
      int col = wn + ni*8 + 2*tg;
      if (t1 >= 0){
        atomicAdd(op1 + col,     acc[mi][ni][0]*w1);
        atomicAdd(op1 + col + 1, acc[mi][ni][1]*w1);
      }
      if (t2 >= 0){
        atomicAdd(op2 + col,     acc[mi][ni][2]*w2);
        atomicAdd(op2 + col + 1, acc[mi][ni][3]*w2);
      }
    }
  }
}

// ---------------- launch ----------------
extern "C" void kernel_launch(void* const* d_in, const int* in_sizes, int n_in,
                              void* d_out, int out_size){
  const float* x     = (const float*)d_in[0];
  const float* gamma = (const float*)d_in[1];
  const float* beta  = (const float*)d_in[2];
  const float* Wr    = (const float*)d_in[3];
  const float* W12   = (const float*)d_in[4];
  const float* W3    = (const float*)d_in[5];
  float* out = (float*)d_out;

  cudaFuncSetAttribute(gemm1_kernel, cudaFuncAttributeMaxDynamicSharedMemorySize, SMEM_BYTES);
  cudaFuncSetAttribute(gemm2_kernel, cudaFuncAttributeMaxDynamicSharedMemorySize, SMEM_BYTES);

  convw_kernel<<<16384, 256>>>((const float4*)W12, (const float4*)W3);
  ln_router_kernel<<<TTOK, 256>>>(x, gamma, beta, Wr);
  hist_kernel<<<64, 256>>>();
  scan_kernel<<<1, 256>>>();
  init_kernel<<<TTOK, 256>>>((float4*)out);
  rank_kernel<<<64, 256>>>();
  gemm1_kernel<<<dim3(CAPACITY/128, DFF/128, NEXP), 256, SMEM_BYTES>>>();
  gemm2_kernel<<<dim3(CAPACITY/128, DMODEL/256, NEXP), 256, SMEM_BYTES>>>(out);
}